// round 10
// baseline (speedup 1.0000x reference)
#include <cuda_runtime.h>
#include <cuda_bf16.h>
#include <math.h>
#include <stdint.h>

#define BATCH 2
#define SLEN  2048
#define HEADS 16
#define HDIM  64
#define EMB   1024
#define ROWS_TOT (BATCH*SLEN)        /* 4096 */
#define OUT_ELEMS (ROWS_TOT*EMB)
#define TABW  4095
#define MSHIFT 20.0f
#define GP 72                         /* smem row pitch in bf16 elems */

// ---------------- scratch (device globals) ---------------------------------
__device__ __nv_bfloat16 g_xh[ROWS_TOT*EMB],  g_xl[ROWS_TOT*EMB];
__device__ __nv_bfloat16 g_whi[4*EMB*EMB],    g_wlo[4*EMB*EMB];   // [n][k]
__device__ __nv_bfloat16 g_qh[ROWS_TOT*EMB],  g_ql[ROWS_TOT*EMB];
__device__ __nv_bfloat16 g_kh[ROWS_TOT*EMB],  g_kl[ROWS_TOT*EMB];
__device__ __nv_bfloat16 g_vh[ROWS_TOT*EMB],  g_vl[ROWS_TOT*EMB];
__device__ __nv_bfloat16 g_aoh[ROWS_TOT*EMB], g_aol[ROWS_TOT*EMB];
__device__ float g_tab[HEADS*TABW];
__device__ float g_tab2[HEADS*TABW];

// ---------------- helpers ---------------------------------------------------
static __device__ __forceinline__ uint32_t smem_u32(const void* p) {
    return (uint32_t)__cvta_generic_to_shared(p);
}
static __device__ __forceinline__ void ldm4(uint32_t* r, uint32_t a) {
    asm volatile("ldmatrix.sync.aligned.m8n8.x4.shared.b16 {%0,%1,%2,%3}, [%4];"
        : "=r"(r[0]), "=r"(r[1]), "=r"(r[2]), "=r"(r[3]) : "r"(a));
}
static __device__ __forceinline__ void ldm4t(uint32_t* r, uint32_t a) {
    asm volatile("ldmatrix.sync.aligned.m8n8.x4.trans.shared.b16 {%0,%1,%2,%3}, [%4];"
        : "=r"(r[0]), "=r"(r[1]), "=r"(r[2]), "=r"(r[3]) : "r"(a));
}
static __device__ __forceinline__ void mma16816(float* c, const uint32_t* a, const uint32_t* b) {
    asm volatile(
        "mma.sync.aligned.m16n8k16.row.col.f32.bf16.bf16.f32 "
        "{%0,%1,%2,%3}, {%4,%5,%6,%7}, {%8,%9}, {%0,%1,%2,%3};"
        : "+f"(c[0]), "+f"(c[1]), "+f"(c[2]), "+f"(c[3])
        : "r"(a[0]), "r"(a[1]), "r"(a[2]), "r"(a[3]), "r"(b[0]), "r"(b[1]));
}
static __device__ __forceinline__ uint32_t pack_bf16x2(float lo, float hi) {
    __nv_bfloat162 t = __floats2bfloat162_rn(lo, hi);
    return *reinterpret_cast<uint32_t*>(&t);
}
static __device__ __forceinline__ float lo_f32(uint32_t u) { return __uint_as_float(u << 16); }
static __device__ __forceinline__ float hi_f32(uint32_t u) { return __uint_as_float(u & 0xffff0000u); }
static __device__ __forceinline__ void split_store2(__nv_bfloat16* H, __nv_bfloat16* L,
                                                    size_t idx, float v0, float v1) {
    __nv_bfloat162 hh = __floats2bfloat162_rn(v0, v1);
    __nv_bfloat162 ll = __floats2bfloat162_rn(v0 - __bfloat162float(hh.x),
                                              v1 - __bfloat162float(hh.y));
    *reinterpret_cast<__nv_bfloat162*>(H + idx) = hh;
    *reinterpret_cast<__nv_bfloat162*>(L + idx) = ll;
}

// ---------------- T5 bucket + bias table ------------------------------------
__device__ __forceinline__ int rel_bucket(int d) {
    int base = (d > 0) ? 16 : 0;
    int rp = abs(d);
    if (rp < 8) return base + rp;
    double v = log((double)rp / 8.0) / log(16.0) * 8.0;
    int b = (int)(v + 1e-6);
    if (b > 7) b = 7;
    return base + 8 + b;
}
__global__ void build_tab_kernel(const float* __restrict__ rel) {
    int idx = blockIdx.x * blockDim.x + threadIdx.x;
    if (idx >= HEADS * TABW) return;
    int h = idx / TABW, dd = idx % TABW;
    float b = rel[rel_bucket(dd - 2047) * HEADS + h];
    g_tab[h * TABW + dd]  = b;
    g_tab2[h * TABW + dd] = b - MSHIFT;
}

// ---------------- input / weight splitting ----------------------------------
__global__ void xsplit_kernel(const float* __restrict__ x) {
    int idx = blockIdx.x * blockDim.x + threadIdx.x;   // float4 id
    float4 v = reinterpret_cast<const float4*>(x)[idx];
    __nv_bfloat162 h0 = __floats2bfloat162_rn(v.x, v.y);
    __nv_bfloat162 h1 = __floats2bfloat162_rn(v.z, v.w);
    __nv_bfloat162 l0 = __floats2bfloat162_rn(v.x - __bfloat162float(h0.x),
                                              v.y - __bfloat162float(h0.y));
    __nv_bfloat162 l1 = __floats2bfloat162_rn(v.z - __bfloat162float(h1.x),
                                              v.w - __bfloat162float(h1.y));
    reinterpret_cast<__nv_bfloat162*>(g_xh)[idx * 2]     = h0;
    reinterpret_cast<__nv_bfloat162*>(g_xh)[idx * 2 + 1] = h1;
    reinterpret_cast<__nv_bfloat162*>(g_xl)[idx * 2]     = l0;
    reinterpret_cast<__nv_bfloat162*>(g_xl)[idx * 2 + 1] = l1;
}
// W[k][n] -> Wt[n][k] hi/lo. grid (32,32,4), block (32,8)
__global__ __launch_bounds__(256) void wsplit_kernel(const float* __restrict__ W0,
                                                     const float* __restrict__ W1,
                                                     const float* __restrict__ W2,
                                                     const float* __restrict__ W3) {
    __shared__ float t[32][33];
    const float* W = (blockIdx.z == 0) ? W0 : (blockIdx.z == 1) ? W1
                   : (blockIdx.z == 2) ? W2 : W3;
    int n0 = blockIdx.x * 32, k0 = blockIdx.y * 32;
#pragma unroll
    for (int i = threadIdx.y; i < 32; i += 8)
        t[i][threadIdx.x] = W[(size_t)(k0 + i) * EMB + n0 + threadIdx.x];
    __syncthreads();
    __nv_bfloat16* hi = g_whi + (size_t)blockIdx.z * EMB * EMB;
    __nv_bfloat16* lo = g_wlo + (size_t)blockIdx.z * EMB * EMB;
#pragma unroll
    for (int i = threadIdx.y; i < 32; i += 8) {
        float v = t[threadIdx.x][i];
        __nv_bfloat16 h = __float2bfloat16(v);
        size_t o = (size_t)(n0 + i) * EMB + k0 + threadIdx.x;
        hi[o] = h;
        lo[o] = __float2bfloat16(v - __bfloat162float(h));
    }
}

// ---------------- tensor-core GEMM (mma.sync, bf16 split) -------------------
#define GAH 0
#define GAL 18432
#define GBH 36864
#define GBL 55296
#define GSTAGEB 73728
#define GEMM_SMEM (2*GSTAGEB)

__device__ __forceinline__ void gemm_body(
    const __nv_bfloat16* __restrict__ Ah, const __nv_bfloat16* __restrict__ Al,
    const __nv_bfloat16* __restrict__ Bh, const __nv_bfloat16* __restrict__ Bl,
    __nv_bfloat16* __restrict__ Oh, __nv_bfloat16* __restrict__ Ol,
    float* __restrict__ Of)
{
    extern __shared__ __align__(16) char smem[];
    const uint32_t sb = smem_u32(smem);
    const int tid = threadIdx.x, lane = tid & 31, wid = tid >> 5;
    const int wm = wid >> 2, wn = wid & 3;
    const int row0 = blockIdx.y * 128, col0 = blockIdx.x * 128;

    const int lrA = (lane & 7) + ((lane >> 3) & 1) * 8;
    const int lcA = (lane >> 4) * 8;
    const int lrB = (lane & 7) + ((lane >> 4) << 3);
    const int lcB = ((lane >> 3) & 1) * 8;

    float c[4][4][4];
#pragma unroll
    for (int a = 0; a < 4; a++)
#pragma unroll
        for (int b = 0; b < 4; b++)
#pragma unroll
            for (int d = 0; d < 4; d++) c[a][b][d] = 0.f;

    uint4 ra_h[4], ra_l[4], rb_h[4], rb_l[4];
    auto loadch = [&](int k0) {
#pragma unroll
        for (int t = 0; t < 4; t++) {
            int fi = tid + t * 256, r = fi >> 3, c8 = (fi & 7) * 8;
            size_t ga = (size_t)(row0 + r) * EMB + k0 + c8;
            size_t gb = (size_t)(col0 + r) * EMB + k0 + c8;
            ra_h[t] = *(const uint4*)(Ah + ga);
            ra_l[t] = *(const uint4*)(Al + ga);
            rb_h[t] = *(const uint4*)(Bh + gb);
            rb_l[t] = *(const uint4*)(Bl + gb);
        }
    };
    auto storech = [&](int s) {
        char* b = smem + s * GSTAGEB;
#pragma unroll
        for (int t = 0; t < 4; t++) {
            int fi = tid + t * 256, r = fi >> 3, c8 = (fi & 7) * 8;
            uint32_t off = (uint32_t)(r * GP + c8) * 2;
            *(uint4*)(b + GAH + off) = ra_h[t];
            *(uint4*)(b + GAL + off) = ra_l[t];
            *(uint4*)(b + GBH + off) = rb_h[t];
            *(uint4*)(b + GBL + off) = rb_l[t];
        }
    };

    loadch(0);
    storech(0);
    __syncthreads();
    int cur = 0;
    for (int ch = 0; ch < 16; ch++) {
        if (ch < 15) loadch((ch + 1) * 64);
        const uint32_t base = sb + cur * GSTAGEB;
#pragma unroll
        for (int kk = 0; kk < 4; kk++) {
            uint32_t ah[4][4], al_[4][4];
#pragma unroll
            for (int mi = 0; mi < 4; mi++) {
                uint32_t ro = (uint32_t)((wm * 64 + mi * 16 + lrA) * GP + kk * 16 + lcA) * 2;
                ldm4(ah[mi],  base + GAH + ro);
                ldm4(al_[mi], base + GAL + ro);
            }
#pragma unroll
            for (int nj2 = 0; nj2 < 2; nj2++) {
                uint32_t bh[4], bl[4];
                uint32_t ro = (uint32_t)((wn * 32 + nj2 * 16 + lrB) * GP + kk * 16 + lcB) * 2;
                ldm4(bh, base + GBH + ro);
                ldm4(bl, base + GBL + ro);
#pragma unroll
                for (int mi = 0; mi < 4; mi++) {
                    mma16816(c[mi][nj2 * 2 + 0], ah[mi],  bh);
                    mma16816(c[mi][nj2 * 2 + 0], ah[mi],  bl);
                    mma16816(c[mi][nj2 * 2 + 0], al_[mi], bh);
                    mma16816(c[mi][nj2 * 2 + 1], ah[mi],  bh + 2);
                    mma16816(c[mi][nj2 * 2 + 1], ah[mi],  bl + 2);
                    mma16816(c[mi][nj2 * 2 + 1], al_[mi], bh + 2);
                }
            }
        }
        if (ch < 15) storech(cur ^ 1);
        __syncthreads();
        cur ^= 1;
    }

#pragma unroll
    for (int mi = 0; mi < 4; mi++)
#pragma unroll
        for (int nj = 0; nj < 4; nj++) {
            int rg = row0 + wm * 64 + mi * 16 + (lane >> 2);
            int cg = col0 + wn * 32 + nj * 8 + (lane & 3) * 2;
            size_t i0 = (size_t)rg * EMB + cg, i1 = (size_t)(rg + 8) * EMB + cg;
            if (Of) {
                *(float2*)(Of + i0) = make_float2(c[mi][nj][0], c[mi][nj][1]);
                *(float2*)(Of + i1) = make_float2(c[mi][nj][2], c[mi][nj][3]);
            } else {
                split_store2(Oh, Ol, i0, c[mi][nj][0], c[mi][nj][1]);
                split_store2(Oh, Ol, i1, c[mi][nj][2], c[mi][nj][3]);
            }
        }
}

__global__ __launch_bounds__(256) void qkv_mma_kernel() {
    int z = blockIdx.z;
    __nv_bfloat16* Oh = (z == 0) ? g_qh : (z == 1) ? g_kh : g_vh;
    __nv_bfloat16* Ol = (z == 0) ? g_ql : (z == 1) ? g_kl : g_vl;
    gemm_body(g_xh, g_xl, g_whi + (size_t)z * EMB * EMB, g_wlo + (size_t)z * EMB * EMB,
              Oh, Ol, nullptr);
}
__global__ __launch_bounds__(256) void out_mma_kernel(float* __restrict__ out) {
    gemm_body(g_aoh, g_aol, g_whi + (size_t)3 * EMB * EMB, g_wlo + (size_t)3 * EMB * EMB,
              nullptr, nullptr, out);
}

// ---------------- flash attention (3-term PV) + fused bias write ------------
#define FQH  0
#define FQL  18432
#define FKV0 36864
#define FSTG 36864
#define FKH  0
#define FKL  9216
#define FVH  18432
#define FVL  27648
#define SMEM_FLASH (FKV0 + 2*FSTG)   /* 110592 */

__global__ __launch_bounds__(256) void flash_kernel(float* __restrict__ bias) {
    extern __shared__ __align__(16) char smem[];
    const uint32_t sb = smem_u32(smem);
    const int tid = threadIdx.x, lane = tid & 31, wid = tid >> 5;
    const int wr0 = wid * 16;
    const int q0 = blockIdx.x * 128, h = blockIdx.y, rowbase = blockIdx.z * SLEN;
    const float* tabh = g_tab2 + h * TABW;
    const float* tabr = g_tab  + h * TABW;

    const int lrA = (lane & 7) + ((lane >> 3) & 1) * 8;
    const int lcA = (lane >> 4) * 8;
    const int lrB = (lane & 7) + ((lane >> 4) << 3);
    const int lcB = ((lane >> 3) & 1) * 8;

    // stage Q (hi/lo) into smem
#pragma unroll
    for (int t = 0; t < 4; t++) {
        int fi = tid + t * 256, r = fi >> 3, c8 = (fi & 7) * 8;
        size_t g = (size_t)(rowbase + q0 + r) * EMB + h * HDIM + c8;
        uint32_t off = (uint32_t)(r * GP + c8) * 2;
        *(uint4*)(smem + FQH + off) = *(const uint4*)(g_qh + g);
        *(uint4*)(smem + FQL + off) = *(const uint4*)(g_ql + g);
    }

    uint4 rk[8];
    auto loadkv = [&](int k0) {
#pragma unroll
        for (int t = 0; t < 2; t++) {
            int fi = tid + t * 256, r = fi >> 3, c8 = (fi & 7) * 8;
            size_t g = (size_t)(rowbase + k0 + r) * EMB + h * HDIM + c8;
            rk[t * 4 + 0] = *(const uint4*)(g_kh + g);
            rk[t * 4 + 1] = *(const uint4*)(g_kl + g);
            rk[t * 4 + 2] = *(const uint4*)(g_vh + g);
            rk[t * 4 + 3] = *(const uint4*)(g_vl + g);
        }
    };
    auto storekv = [&](int s) {
        char* b = smem + FKV0 + s * FSTG;
#pragma unroll
        for (int t = 0; t < 2; t++) {
            int fi = tid + t * 256, r = fi >> 3, c8 = (fi & 7) * 8;
            uint32_t off = (uint32_t)(r * GP + c8) * 2;
            *(uint4*)(b + FKH + off) = rk[t * 4 + 0];
            *(uint4*)(b + FKL + off) = rk[t * 4 + 1];
            *(uint4*)(b + FVH + off) = rk[t * 4 + 2];
            *(uint4*)(b + FVL + off) = rk[t * 4 + 3];
        }
    };
    loadkv(0);
    storekv(0);
    __syncthreads();

    // Q fragments held in registers for all 32 tiles
    uint32_t qh[4][4], ql[4][4];
#pragma unroll
    for (int kb = 0; kb < 4; kb++) {
        uint32_t ro = (uint32_t)((wr0 + lrA) * GP + kb * 16 + lcA) * 2;
        ldm4(qh[kb], sb + FQH + ro);
        ldm4(ql[kb], sb + FQL + ro);
    }

    float o[8][4];
#pragma unroll
    for (int a = 0; a < 8; a++)
#pragma unroll
        for (int d = 0; d < 4; d++) o[a][d] = 0.f;
    float l0 = 0.f, l1 = 0.f;

    int cur = 0;
    const int qa0 = q0 + wr0 + (lane >> 2);
    for (int kt = 0; kt < 32; kt++) {
        const int k0 = kt * 64;
        if (kt < 31) loadkv((kt + 1) * 64);

        // fused position_bias write: batches split the k-range, so each
        // [h][q-tile][k-tile] block is written exactly once grid-wide.
        if ((kt >> 4) == (int)blockIdx.z) {
#pragma unroll
            for (int j = 0; j < 8; j++) {
                int idx = tid + j * 256;
                int r = idx >> 4, c4 = (idx & 15) << 2;
                const float* t = tabr + (k0 + c4) - (q0 + r) + 2047;
                float4 v = make_float4(__ldg(t), __ldg(t + 1), __ldg(t + 2), __ldg(t + 3));
                *(float4*)(bias + ((size_t)(h * SLEN + q0 + r) * SLEN + k0 + c4)) = v;
            }
        }

        const uint32_t kvb = sb + FKV0 + cur * FSTG;

        // ---- S = Q K^T (3-term split) ----
        float sc[8][4];
#pragma unroll
        for (int a = 0; a < 8; a++)
#pragma unroll
            for (int d = 0; d < 4; d++) sc[a][d] = 0.f;
#pragma unroll
        for (int kb = 0; kb < 4; kb++) {
#pragma unroll
            for (int nb2 = 0; nb2 < 4; nb2++) {
                uint32_t bh[4], bl[4];
                uint32_t ro = (uint32_t)((nb2 * 16 + lrB) * GP + kb * 16 + lcB) * 2;
                ldm4(bh, kvb + FKH + ro);
                ldm4(bl, kvb + FKL + ro);
                mma16816(sc[nb2 * 2 + 0], qh[kb], bh);
                mma16816(sc[nb2 * 2 + 0], qh[kb], bl);
                mma16816(sc[nb2 * 2 + 0], ql[kb], bh);
                mma16816(sc[nb2 * 2 + 1], qh[kb], bh + 2);
                mma16816(sc[nb2 * 2 + 1], qh[kb], bl + 2);
                mma16816(sc[nb2 * 2 + 1], ql[kb], bh + 2);
            }
        }

        // ---- softmax (fixed shift), repack P into bf16 hi/lo A-fragments ----
        uint32_t pa[4][4], pl[4][4];
#pragma unroll
        for (int nb = 0; nb < 8; nb++) {
            int cg = k0 + nb * 8 + (lane & 3) * 2;
            int i0 = cg - qa0 + 2047;
            float p00 = __expf(sc[nb][0] + __ldg(tabh + i0));
            float p01 = __expf(sc[nb][1] + __ldg(tabh + i0 + 1));
            float p10 = __expf(sc[nb][2] + __ldg(tabh + i0 - 8));
            float p11 = __expf(sc[nb][3] + __ldg(tabh + i0 - 7));
            l0 += p00 + p01;
            l1 += p10 + p11;
            uint32_t u0 = pack_bf16x2(p00, p01);
            uint32_t u1 = pack_bf16x2(p10, p11);
            int kb = nb >> 1, sl = (nb & 1) * 2;
            pa[kb][sl + 0] = u0;
            pa[kb][sl + 1] = u1;
            pl[kb][sl + 0] = pack_bf16x2(p00 - lo_f32(u0), p01 - hi_f32(u0));
            pl[kb][sl + 1] = pack_bf16x2(p10 - lo_f32(u1), p11 - hi_f32(u1));
        }

        // ---- O += P V (3-term split) ----
#pragma unroll
        for (int kb = 0; kb < 4; kb++) {
#pragma unroll
            for (int nb2 = 0; nb2 < 4; nb2++) {
                uint32_t vh[4], vl[4];
                uint32_t ro = (uint32_t)((kb * 16 + lrA) * GP + nb2 * 16 + lcA) * 2;
                ldm4t(vh, kvb + FVH + ro);
                ldm4t(vl, kvb + FVL + ro);
                mma16816(o[nb2 * 2 + 0], pa[kb], vh);
                mma16816(o[nb2 * 2 + 0], pa[kb], vl);
                mma16816(o[nb2 * 2 + 0], pl[kb], vh);
                mma16816(o[nb2 * 2 + 1], pa[kb], vh + 2);
                mma16816(o[nb2 * 2 + 1], pa[kb], vl + 2);
                mma16816(o[nb2 * 2 + 1], pl[kb], vh + 2);
            }
        }
        if (kt < 31) storekv(cur ^ 1);
        __syncthreads();
        cur ^= 1;
    }

    // reduce row sums over the 4-lane quads, normalize, store split bf16
    l0 += __shfl_xor_sync(0xffffffffu, l0, 1);
    l0 += __shfl_xor_sync(0xffffffffu, l0, 2);
    l1 += __shfl_xor_sync(0xffffffffu, l1, 1);
    l1 += __shfl_xor_sync(0xffffffffu, l1, 2);
    float inv0 = 1.0f / l0, inv1 = 1.0f / l1;
    const int rg = rowbase + q0 + wr0 + (lane >> 2);
#pragma unroll
    for (int nb = 0; nb < 8; nb++) {
        int cg = h * HDIM + nb * 8 + (lane & 3) * 2;
        split_store2(g_aoh, g_aol, (size_t)rg * EMB + cg,
                     o[nb][0] * inv0, o[nb][1] * inv0);
        split_store2(g_aoh, g_aol, (size_t)(rg + 8) * EMB + cg,
                     o[nb][2] * inv1, o[nb][3] * inv1);
    }
}

// ---------------- launch ----------------------------------------------------
extern "C" void kernel_launch(void* const* d_in, const int* in_sizes, int n_in,
                              void* d_out, int out_size) {
    (void)in_sizes; (void)n_in; (void)out_size;
    const float* x   = (const float*)d_in[0];
    const float* Wq  = (const float*)d_in[1];
    const float* Wk  = (const float*)d_in[2];
    const float* Wv  = (const float*)d_in[3];
    const float* Wo  = (const float*)d_in[4];
    const float* rel = (const float*)d_in[5];

    float* out  = (float*)d_out;
    float* bias = out + OUT_ELEMS;

    build_tab_kernel<<<(HEADS * TABW + 255) / 256, 256>>>(rel);
    wsplit_kernel<<<dim3(32, 32, 4), dim3(32, 8)>>>(Wq, Wk, Wv, Wo);
    xsplit_kernel<<<ROWS_TOT * EMB / 4 / 256, 256>>>(x);

    cudaFuncSetAttribute(qkv_mma_kernel, cudaFuncAttributeMaxDynamicSharedMemorySize, GEMM_SMEM);
    cudaFuncSetAttribute(out_mma_kernel, cudaFuncAttributeMaxDynamicSharedMemorySize, GEMM_SMEM);
    cudaFuncSetAttribute(flash_kernel, cudaFuncAttributeMaxDynamicSharedMemorySize, SMEM_FLASH);

    qkv_mma_kernel<<<dim3(8, 32, 3), 256, GEMM_SMEM>>>();
    flash_kernel<<<dim3(SLEN / 128, HEADS, BATCH), 256, SMEM_FLASH>>>(bias);
    out_mma_kernel<<<dim3(8, 32), 256, GEMM_SMEM>>>(out);
}

// round 11
// speedup vs baseline: 1.0504x; 1.0504x over previous
#include <cuda_runtime.h>
#include <cuda_bf16.h>
#include <math.h>
#include <stdint.h>

#define BATCH 2
#define SLEN  2048
#define HEADS 16
#define HDIM  64
#define EMB   1024
#define ROWS_TOT (BATCH*SLEN)        /* 4096 */
#define OUT_ELEMS (ROWS_TOT*EMB)
#define TABW  4095
#define MSHIFT 20.0f
#define GP 72                         /* flash smem row pitch in bf16 elems */

// ---------------- scratch (device globals) ---------------------------------
__device__ __nv_bfloat16 g_xh[ROWS_TOT*EMB],  g_xl[ROWS_TOT*EMB];
__device__ __nv_bfloat16 g_whi[4*EMB*EMB],    g_wlo[4*EMB*EMB];   // [n][k]
__device__ __nv_bfloat16 g_qh[ROWS_TOT*EMB],  g_ql[ROWS_TOT*EMB];
__device__ __nv_bfloat16 g_kh[ROWS_TOT*EMB],  g_kl[ROWS_TOT*EMB];
__device__ __nv_bfloat16 g_vh[ROWS_TOT*EMB],  g_vl[ROWS_TOT*EMB];
__device__ __nv_bfloat16 g_aoh[ROWS_TOT*EMB], g_aol[ROWS_TOT*EMB];
__device__ float g_tab[HEADS*TABW];
__device__ float g_tab2[HEADS*TABW];

// ---------------- helpers ---------------------------------------------------
static __device__ __forceinline__ uint32_t smem_u32(const void* p) {
    return (uint32_t)__cvta_generic_to_shared(p);
}
static __device__ __forceinline__ void cpa16(uint32_t s, const void* g) {
    asm volatile("cp.async.cg.shared.global [%0], [%1], 16;" :: "r"(s), "l"(g));
}
#define CP_COMMIT() asm volatile("cp.async.commit_group;" ::: "memory")
#define CP_WAIT0()  asm volatile("cp.async.wait_group 0;" ::: "memory")
static __device__ __forceinline__ void ldm4(uint32_t* r, uint32_t a) {
    asm volatile("ldmatrix.sync.aligned.m8n8.x4.shared.b16 {%0,%1,%2,%3}, [%4];"
        : "=r"(r[0]), "=r"(r[1]), "=r"(r[2]), "=r"(r[3]) : "r"(a));
}
static __device__ __forceinline__ void ldm4t(uint32_t* r, uint32_t a) {
    asm volatile("ldmatrix.sync.aligned.m8n8.x4.trans.shared.b16 {%0,%1,%2,%3}, [%4];"
        : "=r"(r[0]), "=r"(r[1]), "=r"(r[2]), "=r"(r[3]) : "r"(a));
}
static __device__ __forceinline__ void mma16816(float* c, const uint32_t* a, const uint32_t* b) {
    asm volatile(
        "mma.sync.aligned.m16n8k16.row.col.f32.bf16.bf16.f32 "
        "{%0,%1,%2,%3}, {%4,%5,%6,%7}, {%8,%9}, {%0,%1,%2,%3};"
        : "+f"(c[0]), "+f"(c[1]), "+f"(c[2]), "+f"(c[3])
        : "r"(a[0]), "r"(a[1]), "r"(a[2]), "r"(a[3]), "r"(b[0]), "r"(b[1]));
}
static __device__ __forceinline__ uint32_t pack_bf16x2(float lo, float hi) {
    __nv_bfloat162 t = __floats2bfloat162_rn(lo, hi);
    return *reinterpret_cast<uint32_t*>(&t);
}
static __device__ __forceinline__ float lo_f32(uint32_t u) { return __uint_as_float(u << 16); }
static __device__ __forceinline__ float hi_f32(uint32_t u) { return __uint_as_float(u & 0xffff0000u); }
static __device__ __forceinline__ void split_store2(__nv_bfloat16* H, __nv_bfloat16* L,
                                                    size_t idx, float v0, float v1) {
    __nv_bfloat162 hh = __floats2bfloat162_rn(v0, v1);
    __nv_bfloat162 ll = __floats2bfloat162_rn(v0 - __bfloat162float(hh.x),
                                              v1 - __bfloat162float(hh.y));
    *reinterpret_cast<__nv_bfloat162*>(H + idx) = hh;
    *reinterpret_cast<__nv_bfloat162*>(L + idx) = ll;
}

// ---------------- T5 bucket + bias table ------------------------------------
__device__ __forceinline__ int rel_bucket(int d) {
    int base = (d > 0) ? 16 : 0;
    int rp = abs(d);
    if (rp < 8) return base + rp;
    double v = log((double)rp / 8.0) / log(16.0) * 8.0;
    int b = (int)(v + 1e-6);
    if (b > 7) b = 7;
    return base + 8 + b;
}
__global__ void build_tab_kernel(const float* __restrict__ rel) {
    int idx = blockIdx.x * blockDim.x + threadIdx.x;
    if (idx >= HEADS * TABW) return;
    int h = idx / TABW, dd = idx % TABW;
    float b = rel[rel_bucket(dd - 2047) * HEADS + h];
    g_tab[h * TABW + dd]  = b;
    g_tab2[h * TABW + dd] = b - MSHIFT;
}
__global__ void write_bias_kernel(float* __restrict__ bias) {
    int idx = blockIdx.x * blockDim.x + threadIdx.x;   // one float4 each
    int k4 = idx & 511;
    int q  = (idx >> 9) & 2047;
    int h  = idx >> 20;
    int d  = (k4 << 2) - q + 2047;
    const float* t = g_tab + h * TABW + d;
    float4 v = make_float4(__ldg(t), __ldg(t + 1), __ldg(t + 2), __ldg(t + 3));
    reinterpret_cast<float4*>(bias)[idx] = v;
}

// ---------------- input / weight splitting ----------------------------------
__global__ void xsplit_kernel(const float* __restrict__ x) {
    int idx = blockIdx.x * blockDim.x + threadIdx.x;   // float4 id
    float4 v = reinterpret_cast<const float4*>(x)[idx];
    __nv_bfloat162 h0 = __floats2bfloat162_rn(v.x, v.y);
    __nv_bfloat162 h1 = __floats2bfloat162_rn(v.z, v.w);
    __nv_bfloat162 l0 = __floats2bfloat162_rn(v.x - __bfloat162float(h0.x),
                                              v.y - __bfloat162float(h0.y));
    __nv_bfloat162 l1 = __floats2bfloat162_rn(v.z - __bfloat162float(h1.x),
                                              v.w - __bfloat162float(h1.y));
    reinterpret_cast<__nv_bfloat162*>(g_xh)[idx * 2]     = h0;
    reinterpret_cast<__nv_bfloat162*>(g_xh)[idx * 2 + 1] = h1;
    reinterpret_cast<__nv_bfloat162*>(g_xl)[idx * 2]     = l0;
    reinterpret_cast<__nv_bfloat162*>(g_xl)[idx * 2 + 1] = l1;
}
// W[k][n] -> Wt[n][k] hi/lo. grid (32,32,4), block (32,8)
__global__ __launch_bounds__(256) void wsplit_kernel(const float* __restrict__ W0,
                                                     const float* __restrict__ W1,
                                                     const float* __restrict__ W2,
                                                     const float* __restrict__ W3) {
    __shared__ float t[32][33];
    const float* W = (blockIdx.z == 0) ? W0 : (blockIdx.z == 1) ? W1
                   : (blockIdx.z == 2) ? W2 : W3;
    int n0 = blockIdx.x * 32, k0 = blockIdx.y * 32;
#pragma unroll
    for (int i = threadIdx.y; i < 32; i += 8)
        t[i][threadIdx.x] = W[(size_t)(k0 + i) * EMB + n0 + threadIdx.x];
    __syncthreads();
    __nv_bfloat16* hi = g_whi + (size_t)blockIdx.z * EMB * EMB;
    __nv_bfloat16* lo = g_wlo + (size_t)blockIdx.z * EMB * EMB;
#pragma unroll
    for (int i = threadIdx.y; i < 32; i += 8) {
        float v = t[threadIdx.x][i];
        __nv_bfloat16 h = __float2bfloat16(v);
        size_t o = (size_t)(n0 + i) * EMB + k0 + threadIdx.x;
        hi[o] = h;
        lo[o] = __float2bfloat16(v - __bfloat162float(h));
    }
}

// ---------------- tensor-core GEMM (cp.async, kc=32, 2 CTAs/SM) -------------
#define KC 32
#define TP 40                         /* gemm smem pitch (conflict-free) */
#define TILEB (128*TP*2)              /* 10240 */
#define GAH 0
#define GAL TILEB
#define GBH (2*TILEB)
#define GBL (3*TILEB)
#define GSTAGEB (4*TILEB)             /* 40960 */
#define GEMM_SMEM (2*GSTAGEB)         /* 81920 */

__device__ __forceinline__ void gemm_body(
    const __nv_bfloat16* __restrict__ Ah, const __nv_bfloat16* __restrict__ Al,
    const __nv_bfloat16* __restrict__ Bh, const __nv_bfloat16* __restrict__ Bl,
    __nv_bfloat16* __restrict__ Oh, __nv_bfloat16* __restrict__ Ol,
    float* __restrict__ Of)
{
    extern __shared__ __align__(16) char smem[];
    const uint32_t sb = smem_u32(smem);
    const int tid = threadIdx.x, lane = tid & 31, wid = tid >> 5;
    const int wm = wid >> 2, wn = wid & 3;
    const int row0 = blockIdx.y * 128, col0 = blockIdx.x * 128;

    const int lrA = (lane & 7) + ((lane >> 3) & 1) * 8;
    const int lcA = (lane >> 4) * 8;
    const int lrB = (lane & 7) + ((lane >> 4) << 3);
    const int lcB = ((lane >> 3) & 1) * 8;

    float c[4][4][4];
#pragma unroll
    for (int a = 0; a < 4; a++)
#pragma unroll
        for (int b = 0; b < 4; b++)
#pragma unroll
            for (int d = 0; d < 4; d++) c[a][b][d] = 0.f;

    auto loadch = [&](int k0, int s) {
        uint32_t b = sb + s * GSTAGEB;
#pragma unroll
        for (int t = 0; t < 2; t++) {
            int fi = tid + t * 256;
            int r = fi >> 2, c8 = (fi & 3) * 8;
            uint32_t so = (uint32_t)(r * TP + c8) * 2;
            size_t ga = (size_t)(row0 + r) * EMB + k0 + c8;
            size_t gb = (size_t)(col0 + r) * EMB + k0 + c8;
            cpa16(b + GAH + so, Ah + ga);
            cpa16(b + GAL + so, Al + ga);
            cpa16(b + GBH + so, Bh + gb);
            cpa16(b + GBL + so, Bl + gb);
        }
        CP_COMMIT();
    };

    loadch(0, 0);
    CP_WAIT0();
    __syncthreads();
    int cur = 0;
    for (int ch = 0; ch < 32; ch++) {
        if (ch < 31) loadch((ch + 1) * KC, cur ^ 1);
        const uint32_t base = sb + cur * GSTAGEB;
#pragma unroll
        for (int kk = 0; kk < 2; kk++) {
            uint32_t ah[4][4], al_[4][4];
#pragma unroll
            for (int mi = 0; mi < 4; mi++) {
                uint32_t ro = (uint32_t)((wm * 64 + mi * 16 + lrA) * TP + kk * 16 + lcA) * 2;
                ldm4(ah[mi],  base + GAH + ro);
                ldm4(al_[mi], base + GAL + ro);
            }
#pragma unroll
            for (int nj2 = 0; nj2 < 2; nj2++) {
                uint32_t bh[4], bl[4];
                uint32_t ro = (uint32_t)((wn * 32 + nj2 * 16 + lrB) * TP + kk * 16 + lcB) * 2;
                ldm4(bh, base + GBH + ro);
                ldm4(bl, base + GBL + ro);
#pragma unroll
                for (int mi = 0; mi < 4; mi++) {
                    mma16816(c[mi][nj2 * 2 + 0], ah[mi],  bh);
                    mma16816(c[mi][nj2 * 2 + 0], ah[mi],  bl);
                    mma16816(c[mi][nj2 * 2 + 0], al_[mi], bh);
                    mma16816(c[mi][nj2 * 2 + 1], ah[mi],  bh + 2);
                    mma16816(c[mi][nj2 * 2 + 1], ah[mi],  bl + 2);
                    mma16816(c[mi][nj2 * 2 + 1], al_[mi], bh + 2);
                }
            }
        }
        if (ch < 31) CP_WAIT0();
        __syncthreads();
        cur ^= 1;
    }

#pragma unroll
    for (int mi = 0; mi < 4; mi++)
#pragma unroll
        for (int nj = 0; nj < 4; nj++) {
            int rg = row0 + wm * 64 + mi * 16 + (lane >> 2);
            int cg = col0 + wn * 32 + nj * 8 + (lane & 3) * 2;
            size_t i0 = (size_t)rg * EMB + cg, i1 = (size_t)(rg + 8) * EMB + cg;
            if (Of) {
                *(float2*)(Of + i0) = make_float2(c[mi][nj][0], c[mi][nj][1]);
                *(float2*)(Of + i1) = make_float2(c[mi][nj][2], c[mi][nj][3]);
            } else {
                split_store2(Oh, Ol, i0, c[mi][nj][0], c[mi][nj][1]);
                split_store2(Oh, Ol, i1, c[mi][nj][2], c[mi][nj][3]);
            }
        }
}

__global__ __launch_bounds__(256, 2) void qkv_mma_kernel() {
    int z = blockIdx.z;
    __nv_bfloat16* Oh = (z == 0) ? g_qh : (z == 1) ? g_kh : g_vh;
    __nv_bfloat16* Ol = (z == 0) ? g_ql : (z == 1) ? g_kl : g_vl;
    gemm_body(g_xh, g_xl, g_whi + (size_t)z * EMB * EMB, g_wlo + (size_t)z * EMB * EMB,
              Oh, Ol, nullptr);
}
__global__ __launch_bounds__(256, 2) void out_mma_kernel(float* __restrict__ out) {
    gemm_body(g_aoh, g_aol, g_whi + (size_t)3 * EMB * EMB, g_wlo + (size_t)3 * EMB * EMB,
              nullptr, nullptr, out);
}

// ---------------- flash attention (3-term PV, cp.async, 2 CTAs/SM) ----------
#define FQH  0
#define FQL  18432
#define FKV0 36864
#define FSTG 36864
#define FKH  0
#define FKL  9216
#define FVH  18432
#define FVL  27648
#define SMEM_FLASH (FKV0 + 2*FSTG)   /* 110592 */

__global__ __launch_bounds__(256, 2) void flash_kernel() {
    extern __shared__ __align__(16) char smem[];
    const uint32_t sb = smem_u32(smem);
    const int tid = threadIdx.x, lane = tid & 31, wid = tid >> 5;
    const int wr0 = wid * 16;
    const int q0 = blockIdx.x * 128, h = blockIdx.y, rowbase = blockIdx.z * SLEN;
    const float* tabh = g_tab2 + h * TABW;

    const int lrA = (lane & 7) + ((lane >> 3) & 1) * 8;
    const int lcA = (lane >> 4) * 8;
    const int lrB = (lane & 7) + ((lane >> 4) << 3);
    const int lcB = ((lane >> 3) & 1) * 8;

    auto loadkv = [&](int k0, int s) {
        uint32_t b = sb + FKV0 + s * FSTG;
#pragma unroll
        for (int t = 0; t < 2; t++) {
            int fi = tid + t * 256;
            int r = fi >> 3, c8 = (fi & 7) * 8;
            uint32_t so = (uint32_t)(r * GP + c8) * 2;
            size_t g = (size_t)(rowbase + k0 + r) * EMB + h * HDIM + c8;
            cpa16(b + FKH + so, g_kh + g);
            cpa16(b + FKL + so, g_kl + g);
            cpa16(b + FVH + so, g_vh + g);
            cpa16(b + FVL + so, g_vl + g);
        }
        CP_COMMIT();
    };

    loadkv(0, 0);
    // stage Q (hi/lo) into smem with plain stores
#pragma unroll
    for (int t = 0; t < 4; t++) {
        int fi = tid + t * 256, r = fi >> 3, c8 = (fi & 7) * 8;
        size_t g = (size_t)(rowbase + q0 + r) * EMB + h * HDIM + c8;
        uint32_t off = (uint32_t)(r * GP + c8) * 2;
        *(uint4*)(smem + FQH + off) = *(const uint4*)(g_qh + g);
        *(uint4*)(smem + FQL + off) = *(const uint4*)(g_ql + g);
    }
    CP_WAIT0();
    __syncthreads();

    // Q fragments held in registers for all 32 tiles
    uint32_t qh[4][4], ql[4][4];
#pragma unroll
    for (int kb = 0; kb < 4; kb++) {
        uint32_t ro = (uint32_t)((wr0 + lrA) * GP + kb * 16 + lcA) * 2;
        ldm4(qh[kb], sb + FQH + ro);
        ldm4(ql[kb], sb + FQL + ro);
    }

    float o[8][4];
#pragma unroll
    for (int a = 0; a < 8; a++)
#pragma unroll
        for (int d = 0; d < 4; d++) o[a][d] = 0.f;
    float l0 = 0.f, l1 = 0.f;

    int cur = 0;
    const int qa0 = q0 + wr0 + (lane >> 2);
    for (int kt = 0; kt < 32; kt++) {
        const int k0 = kt * 64;
        if (kt < 31) loadkv((kt + 1) * 64, cur ^ 1);
        const uint32_t kvb = sb + FKV0 + cur * FSTG;

        // ---- S = Q K^T (3-term split) ----
        float sc[8][4];
#pragma unroll
        for (int a = 0; a < 8; a++)
#pragma unroll
            for (int d = 0; d < 4; d++) sc[a][d] = 0.f;
#pragma unroll
        for (int kb = 0; kb < 4; kb++) {
#pragma unroll
            for (int nb2 = 0; nb2 < 4; nb2++) {
                uint32_t bh[4], bl[4];
                uint32_t ro = (uint32_t)((nb2 * 16 + lrB) * GP + kb * 16 + lcB) * 2;
                ldm4(bh, kvb + FKH + ro);
                ldm4(bl, kvb + FKL + ro);
                mma16816(sc[nb2 * 2 + 0], qh[kb], bh);
                mma16816(sc[nb2 * 2 + 0], qh[kb], bl);
                mma16816(sc[nb2 * 2 + 0], ql[kb], bh);
                mma16816(sc[nb2 * 2 + 1], qh[kb], bh + 2);
                mma16816(sc[nb2 * 2 + 1], qh[kb], bl + 2);
                mma16816(sc[nb2 * 2 + 1], ql[kb], bh + 2);
            }
        }

        // ---- softmax (fixed shift), repack P into bf16 hi/lo A-fragments ----
        uint32_t pa[4][4], pl[4][4];
#pragma unroll
        for (int nb = 0; nb < 8; nb++) {
            int cg = k0 + nb * 8 + (lane & 3) * 2;
            int i0 = cg - qa0 + 2047;
            float p00 = __expf(sc[nb][0] + __ldg(tabh + i0));
            float p01 = __expf(sc[nb][1] + __ldg(tabh + i0 + 1));
            float p10 = __expf(sc[nb][2] + __ldg(tabh + i0 - 8));
            float p11 = __expf(sc[nb][3] + __ldg(tabh + i0 - 7));
            l0 += p00 + p01;
            l1 += p10 + p11;
            uint32_t u0 = pack_bf16x2(p00, p01);
            uint32_t u1 = pack_bf16x2(p10, p11);
            int kb = nb >> 1, sl = (nb & 1) * 2;
            pa[kb][sl + 0] = u0;
            pa[kb][sl + 1] = u1;
            pl[kb][sl + 0] = pack_bf16x2(p00 - lo_f32(u0), p01 - hi_f32(u0));
            pl[kb][sl + 1] = pack_bf16x2(p10 - lo_f32(u1), p11 - hi_f32(u1));
        }

        // ---- O += P V (3-term split) ----
#pragma unroll
        for (int kb = 0; kb < 4; kb++) {
#pragma unroll
            for (int nb2 = 0; nb2 < 4; nb2++) {
                uint32_t vh[4], vl[4];
                uint32_t ro = (uint32_t)((kb * 16 + lrA) * GP + nb2 * 16 + lcA) * 2;
                ldm4t(vh, kvb + FVH + ro);
                ldm4t(vl, kvb + FVL + ro);
                mma16816(o[nb2 * 2 + 0], pa[kb], vh);
                mma16816(o[nb2 * 2 + 0], pa[kb], vl);
                mma16816(o[nb2 * 2 + 0], pl[kb], vh);
                mma16816(o[nb2 * 2 + 1], pa[kb], vh + 2);
                mma16816(o[nb2 * 2 + 1], pa[kb], vl + 2);
                mma16816(o[nb2 * 2 + 1], pl[kb], vh + 2);
            }
        }
        if (kt < 31) CP_WAIT0();
        __syncthreads();
        cur ^= 1;
    }

    // reduce row sums over the 4-lane quads, normalize, store split bf16
    l0 += __shfl_xor_sync(0xffffffffu, l0, 1);
    l0 += __shfl_xor_sync(0xffffffffu, l0, 2);
    l1 += __shfl_xor_sync(0xffffffffu, l1, 1);
    l1 += __shfl_xor_sync(0xffffffffu, l1, 2);
    float inv0 = 1.0f / l0, inv1 = 1.0f / l1;
    const int rg = rowbase + q0 + wr0 + (lane >> 2);
#pragma unroll
    for (int nb = 0; nb < 8; nb++) {
        int cg = h * HDIM + nb * 8 + (lane & 3) * 2;
        split_store2(g_aoh, g_aol, (size_t)rg * EMB + cg,
                     o[nb][0] * inv0, o[nb][1] * inv0);
        split_store2(g_aoh, g_aol, (size_t)(rg + 8) * EMB + cg,
                     o[nb][2] * inv1, o[nb][3] * inv1);
    }
}

// ---------------- launch ----------------------------------------------------
extern "C" void kernel_launch(void* const* d_in, const int* in_sizes, int n_in,
                              void* d_out, int out_size) {
    (void)in_sizes; (void)n_in; (void)out_size;
    const float* x   = (const float*)d_in[0];
    const float* Wq  = (const float*)d_in[1];
    const float* Wk  = (const float*)d_in[2];
    const float* Wv  = (const float*)d_in[3];
    const float* Wo  = (const float*)d_in[4];
    const float* rel = (const float*)d_in[5];

    float* out  = (float*)d_out;
    float* bias = out + OUT_ELEMS;

    build_tab_kernel<<<(HEADS * TABW + 255) / 256, 256>>>(rel);
    write_bias_kernel<<<(HEADS * SLEN * SLEN / 4) / 256, 256>>>(bias);
    wsplit_kernel<<<dim3(32, 32, 4), dim3(32, 8)>>>(Wq, Wk, Wv, Wo);
    xsplit_kernel<<<ROWS_TOT * EMB / 4 / 256, 256>>>(x);

    cudaFuncSetAttribute(qkv_mma_kernel, cudaFuncAttributeMaxDynamicSharedMemorySize, GEMM_SMEM);
    cudaFuncSetAttribute(out_mma_kernel, cudaFuncAttributeMaxDynamicSharedMemorySize, GEMM_SMEM);
    cudaFuncSetAttribute(flash_kernel, cudaFuncAttributeMaxDynamicSharedMemorySize, SMEM_FLASH);

    qkv_mma_kernel<<<dim3(8, 32, 3), 256, GEMM_SMEM>>>();
    flash_kernel<<<dim3(SLEN / 128, HEADS, BATCH), 256, SMEM_FLASH>>>();
    out_mma_kernel<<<dim3(8, 32), 256, GEMM_SMEM>>>(out);
}

// round 12
// speedup vs baseline: 1.1080x; 1.0548x over previous
#include <cuda_runtime.h>
#include <cuda_bf16.h>
#include <math.h>
#include <stdint.h>

#define BATCH 2
#define SLEN  2048
#define HEADS 16
#define HDIM  64
#define EMB   1024
#define ROWS_TOT (BATCH*SLEN)        /* 4096 */
#define OUT_ELEMS (ROWS_TOT*EMB)
#define TABW  4095
#define MSHIFT 20.0f
#define GP 72                         /* flash smem row pitch in bf16 elems */

// ---------------- scratch (device globals) ---------------------------------
__device__ __nv_bfloat16 g_xh[ROWS_TOT*EMB],  g_xl[ROWS_TOT*EMB];
__device__ __nv_bfloat16 g_whi[4*EMB*EMB],    g_wlo[4*EMB*EMB];   // [n][k]
__device__ __nv_bfloat16 g_qh[ROWS_TOT*EMB],  g_ql[ROWS_TOT*EMB];
__device__ __nv_bfloat16 g_kh[ROWS_TOT*EMB],  g_kl[ROWS_TOT*EMB];
__device__ __nv_bfloat16 g_vh[ROWS_TOT*EMB],  g_vl[ROWS_TOT*EMB];
__device__ __nv_bfloat16 g_aoh[ROWS_TOT*EMB], g_aol[ROWS_TOT*EMB];
__device__ float g_tab[HEADS*TABW];
__device__ float g_tab2[HEADS*TABW];

// ---------------- helpers ---------------------------------------------------
static __device__ __forceinline__ uint32_t smem_u32(const void* p) {
    return (uint32_t)__cvta_generic_to_shared(p);
}
static __device__ __forceinline__ void cpa16(uint32_t s, const void* g) {
    asm volatile("cp.async.cg.shared.global [%0], [%1], 16;" :: "r"(s), "l"(g));
}
static __device__ __forceinline__ void cpa4(uint32_t s, const void* g) {
    asm volatile("cp.async.ca.shared.global [%0], [%1], 4;" :: "r"(s), "l"(g));
}
#define CP_COMMIT() asm volatile("cp.async.commit_group;" ::: "memory")
#define CP_WAIT0()  asm volatile("cp.async.wait_group 0;" ::: "memory")
static __device__ __forceinline__ void ldm4(uint32_t* r, uint32_t a) {
    asm volatile("ldmatrix.sync.aligned.m8n8.x4.shared.b16 {%0,%1,%2,%3}, [%4];"
        : "=r"(r[0]), "=r"(r[1]), "=r"(r[2]), "=r"(r[3]) : "r"(a));
}
static __device__ __forceinline__ void ldm4t(uint32_t* r, uint32_t a) {
    asm volatile("ldmatrix.sync.aligned.m8n8.x4.trans.shared.b16 {%0,%1,%2,%3}, [%4];"
        : "=r"(r[0]), "=r"(r[1]), "=r"(r[2]), "=r"(r[3]) : "r"(a));
}
static __device__ __forceinline__ void mma16816(float* c, const uint32_t* a, const uint32_t* b) {
    asm volatile(
        "mma.sync.aligned.m16n8k16.row.col.f32.bf16.bf16.f32 "
        "{%0,%1,%2,%3}, {%4,%5,%6,%7}, {%8,%9}, {%0,%1,%2,%3};"
        : "+f"(c[0]), "+f"(c[1]), "+f"(c[2]), "+f"(c[3])
        : "r"(a[0]), "r"(a[1]), "r"(a[2]), "r"(a[3]), "r"(b[0]), "r"(b[1]));
}
static __device__ __forceinline__ uint32_t pack_bf16x2(float lo, float hi) {
    __nv_bfloat162 t = __floats2bfloat162_rn(lo, hi);
    return *reinterpret_cast<uint32_t*>(&t);
}
static __device__ __forceinline__ float lo_f32(uint32_t u) { return __uint_as_float(u << 16); }
static __device__ __forceinline__ float hi_f32(uint32_t u) { return __uint_as_float(u & 0xffff0000u); }
static __device__ __forceinline__ void split_store2(__nv_bfloat16* H, __nv_bfloat16* L,
                                                    size_t idx, float v0, float v1) {
    __nv_bfloat162 hh = __floats2bfloat162_rn(v0, v1);
    __nv_bfloat162 ll = __floats2bfloat162_rn(v0 - __bfloat162float(hh.x),
                                              v1 - __bfloat162float(hh.y));
    *reinterpret_cast<__nv_bfloat162*>(H + idx) = hh;
    *reinterpret_cast<__nv_bfloat162*>(L + idx) = ll;
}

// ---------------- T5 bucket + bias table ------------------------------------
__device__ __forceinline__ int rel_bucket(int d) {
    int base = (d > 0) ? 16 : 0;
    int rp = abs(d);
    if (rp < 8) return base + rp;
    double v = log((double)rp / 8.0) / log(16.0) * 8.0;
    int b = (int)(v + 1e-6);
    if (b > 7) b = 7;
    return base + 8 + b;
}
__global__ void build_tab_kernel(const float* __restrict__ rel) {
    int idx = blockIdx.x * blockDim.x + threadIdx.x;
    if (idx >= HEADS * TABW) return;
    int h = idx / TABW, dd = idx % TABW;
    float b = rel[rel_bucket(dd - 2047) * HEADS + h];
    g_tab[h * TABW + dd]  = b;
    g_tab2[h * TABW + dd] = b - MSHIFT;
}

// ---------------- input / weight splitting ----------------------------------
__global__ void xsplit_kernel(const float* __restrict__ x) {
    int idx = blockIdx.x * blockDim.x + threadIdx.x;   // float4 id
    float4 v = reinterpret_cast<const float4*>(x)[idx];
    __nv_bfloat162 h0 = __floats2bfloat162_rn(v.x, v.y);
    __nv_bfloat162 h1 = __floats2bfloat162_rn(v.z, v.w);
    __nv_bfloat162 l0 = __floats2bfloat162_rn(v.x - __bfloat162float(h0.x),
                                              v.y - __bfloat162float(h0.y));
    __nv_bfloat162 l1 = __floats2bfloat162_rn(v.z - __bfloat162float(h1.x),
                                              v.w - __bfloat162float(h1.y));
    reinterpret_cast<__nv_bfloat162*>(g_xh)[idx * 2]     = h0;
    reinterpret_cast<__nv_bfloat162*>(g_xh)[idx * 2 + 1] = h1;
    reinterpret_cast<__nv_bfloat162*>(g_xl)[idx * 2]     = l0;
    reinterpret_cast<__nv_bfloat162*>(g_xl)[idx * 2 + 1] = l1;
}
// W[k][n] -> Wt[n][k] hi/lo. grid (32,32,4), block (32,8)
__global__ __launch_bounds__(256) void wsplit_kernel(const float* __restrict__ W0,
                                                     const float* __restrict__ W1,
                                                     const float* __restrict__ W2,
                                                     const float* __restrict__ W3) {
    __shared__ float t[32][33];
    const float* W = (blockIdx.z == 0) ? W0 : (blockIdx.z == 1) ? W1
                   : (blockIdx.z == 2) ? W2 : W3;
    int n0 = blockIdx.x * 32, k0 = blockIdx.y * 32;
#pragma unroll
    for (int i = threadIdx.y; i < 32; i += 8)
        t[i][threadIdx.x] = W[(size_t)(k0 + i) * EMB + n0 + threadIdx.x];
    __syncthreads();
    __nv_bfloat16* hi = g_whi + (size_t)blockIdx.z * EMB * EMB;
    __nv_bfloat16* lo = g_wlo + (size_t)blockIdx.z * EMB * EMB;
#pragma unroll
    for (int i = threadIdx.y; i < 32; i += 8) {
        float v = t[threadIdx.x][i];
        __nv_bfloat16 h = __float2bfloat16(v);
        size_t o = (size_t)(n0 + i) * EMB + k0 + threadIdx.x;
        hi[o] = h;
        lo[o] = __float2bfloat16(v - __bfloat162float(h));
    }
}

// ---------------- tensor-core GEMM (cp.async, kc=32, 2 CTAs/SM) -------------
#define KC 32
#define TP 40                         /* gemm smem pitch (conflict-free) */
#define TILEB (128*TP*2)              /* 10240 */
#define GAH 0
#define GAL TILEB
#define GBH (2*TILEB)
#define GBL (3*TILEB)
#define GSTAGEB (4*TILEB)             /* 40960 */
#define GEMM_SMEM (2*GSTAGEB)         /* 81920 */

__device__ __forceinline__ void gemm_body(
    const __nv_bfloat16* __restrict__ Ah, const __nv_bfloat16* __restrict__ Al,
    const __nv_bfloat16* __restrict__ Bh, const __nv_bfloat16* __restrict__ Bl,
    __nv_bfloat16* __restrict__ Oh, __nv_bfloat16* __restrict__ Ol,
    float* __restrict__ Of)
{
    extern __shared__ __align__(16) char smem[];
    const uint32_t sb = smem_u32(smem);
    const int tid = threadIdx.x, lane = tid & 31, wid = tid >> 5;
    const int wm = wid >> 2, wn = wid & 3;
    const int row0 = blockIdx.y * 128, col0 = blockIdx.x * 128;

    const int lrA = (lane & 7) + ((lane >> 3) & 1) * 8;
    const int lcA = (lane >> 4) * 8;
    const int lrB = (lane & 7) + ((lane >> 4) << 3);
    const int lcB = ((lane >> 3) & 1) * 8;

    float c[4][4][4];
#pragma unroll
    for (int a = 0; a < 4; a++)
#pragma unroll
        for (int b = 0; b < 4; b++)
#pragma unroll
            for (int d = 0; d < 4; d++) c[a][b][d] = 0.f;

    auto loadch = [&](int k0, int s) {
        uint32_t b = sb + s * GSTAGEB;
#pragma unroll
        for (int t = 0; t < 2; t++) {
            int fi = tid + t * 256;
            int r = fi >> 2, c8 = (fi & 3) * 8;
            uint32_t so = (uint32_t)(r * TP + c8) * 2;
            size_t ga = (size_t)(row0 + r) * EMB + k0 + c8;
            size_t gb = (size_t)(col0 + r) * EMB + k0 + c8;
            cpa16(b + GAH + so, Ah + ga);
            cpa16(b + GAL + so, Al + ga);
            cpa16(b + GBH + so, Bh + gb);
            cpa16(b + GBL + so, Bl + gb);
        }
        CP_COMMIT();
    };

    loadch(0, 0);
    CP_WAIT0();
    __syncthreads();
    int cur = 0;
    for (int ch = 0; ch < 32; ch++) {
        if (ch < 31) loadch((ch + 1) * KC, cur ^ 1);
        const uint32_t base = sb + cur * GSTAGEB;
#pragma unroll
        for (int kk = 0; kk < 2; kk++) {
            uint32_t ah[4][4], al_[4][4];
#pragma unroll
            for (int mi = 0; mi < 4; mi++) {
                uint32_t ro = (uint32_t)((wm * 64 + mi * 16 + lrA) * TP + kk * 16 + lcA) * 2;
                ldm4(ah[mi],  base + GAH + ro);
                ldm4(al_[mi], base + GAL + ro);
            }
#pragma unroll
            for (int nj2 = 0; nj2 < 2; nj2++) {
                uint32_t bh[4], bl[4];
                uint32_t ro = (uint32_t)((wn * 32 + nj2 * 16 + lrB) * TP + kk * 16 + lcB) * 2;
                ldm4(bh, base + GBH + ro);
                ldm4(bl, base + GBL + ro);
#pragma unroll
                for (int mi = 0; mi < 4; mi++) {
                    mma16816(c[mi][nj2 * 2 + 0], ah[mi],  bh);
                    mma16816(c[mi][nj2 * 2 + 0], ah[mi],  bl);
                    mma16816(c[mi][nj2 * 2 + 0], al_[mi], bh);
                    mma16816(c[mi][nj2 * 2 + 1], ah[mi],  bh + 2);
                    mma16816(c[mi][nj2 * 2 + 1], ah[mi],  bl + 2);
                    mma16816(c[mi][nj2 * 2 + 1], al_[mi], bh + 2);
                }
            }
        }
        if (ch < 31) CP_WAIT0();
        __syncthreads();
        cur ^= 1;
    }

#pragma unroll
    for (int mi = 0; mi < 4; mi++)
#pragma unroll
        for (int nj = 0; nj < 4; nj++) {
            int rg = row0 + wm * 64 + mi * 16 + (lane >> 2);
            int cg = col0 + wn * 32 + nj * 8 + (lane & 3) * 2;
            size_t i0 = (size_t)rg * EMB + cg, i1 = (size_t)(rg + 8) * EMB + cg;
            if (Of) {
                *(float2*)(Of + i0) = make_float2(c[mi][nj][0], c[mi][nj][1]);
                *(float2*)(Of + i1) = make_float2(c[mi][nj][2], c[mi][nj][3]);
            } else {
                split_store2(Oh, Ol, i0, c[mi][nj][0], c[mi][nj][1]);
                split_store2(Oh, Ol, i1, c[mi][nj][2], c[mi][nj][3]);
            }
        }
}

// qkv GEMM + fire-and-forget position_bias stores in the prologue.
// 768 CTAs split the 16.8M float4 bias stream; __stcs avoids L2 pollution.
__global__ __launch_bounds__(256, 2) void qkv_mma_kernel(float* __restrict__ bias) {
    const int tid = threadIdx.x;
    const int cta = ((int)blockIdx.z << 8) + ((int)blockIdx.y << 3) + (int)blockIdx.x;
    for (uint32_t i = (uint32_t)cta * 256 + tid; i < (1u << 24); i += 768u * 256u) {
        uint32_t k4 = i & 511, q = (i >> 9) & 2047, h = i >> 20;
        int d = (int)(k4 << 2) - (int)q + 2047;
        const float* t = g_tab + h * TABW + d;
        float4 v = make_float4(__ldg(t), __ldg(t + 1), __ldg(t + 2), __ldg(t + 3));
        __stcs(reinterpret_cast<float4*>(bias) + i, v);
    }

    int z = blockIdx.z;
    __nv_bfloat16* Oh = (z == 0) ? g_qh : (z == 1) ? g_kh : g_vh;
    __nv_bfloat16* Ol = (z == 0) ? g_ql : (z == 1) ? g_kl : g_vl;
    gemm_body(g_xh, g_xl, g_whi + (size_t)z * EMB * EMB, g_wlo + (size_t)z * EMB * EMB,
              Oh, Ol, nullptr);
}
__global__ __launch_bounds__(256, 2) void out_mma_kernel(float* __restrict__ out) {
    gemm_body(g_aoh, g_aol, g_whi + (size_t)3 * EMB * EMB, g_wlo + (size_t)3 * EMB * EMB,
              nullptr, nullptr, out);
}

// ---------------- flash attention (3-term PV, cp.async, 2 CTAs/SM) ----------
#define FQH  0
#define FQL  18432
#define FKV0 36864
#define FSTG 36864
#define FKH  0
#define FKL  9216
#define FVH  18432
#define FVL  27648
#define FTAB (FKV0 + 2*FSTG)          /* bias windows: 2 stages x 192 floats */
#define SMEM_FLASH (FTAB + 2*192*4)   /* 112128 */

__global__ __launch_bounds__(256, 2) void flash_kernel() {
    extern __shared__ __align__(16) char smem[];
    const uint32_t sb = smem_u32(smem);
    const int tid = threadIdx.x, lane = tid & 31, wid = tid >> 5;
    const int wr0 = wid * 16;
    const int q0 = blockIdx.x * 128, h = blockIdx.y, rowbase = blockIdx.z * SLEN;
    const float* tabh = g_tab2 + h * TABW;

    const int lrA = (lane & 7) + ((lane >> 3) & 1) * 8;
    const int lcA = (lane >> 4) * 8;
    const int lrB = (lane & 7) + ((lane >> 4) << 3);
    const int lcB = ((lane >> 3) & 1) * 8;

    auto loadkv = [&](int kt, int s) {
        const int k0 = kt * 64;
        uint32_t b = sb + FKV0 + s * FSTG;
#pragma unroll
        for (int t = 0; t < 2; t++) {
            int fi = tid + t * 256;
            int r = fi >> 3, c8 = (fi & 7) * 8;
            uint32_t so = (uint32_t)(r * GP + c8) * 2;
            size_t g = (size_t)(rowbase + k0 + r) * EMB + h * HDIM + c8;
            cpa16(b + FKH + so, g_kh + g);
            cpa16(b + FKL + so, g_kl + g);
            cpa16(b + FVH + so, g_vh + g);
            cpa16(b + FVL + so, g_vl + g);
        }
        if (tid < 192) {     // stage this tile's 192-float bias window
            int idx = (k0 - q0 + 1920) + tid;
            if (idx > TABW - 1) idx = TABW - 1;
            cpa4(sb + FTAB + s * 768 + tid * 4, tabh + idx);
        }
        CP_COMMIT();
    };

    loadkv(0, 0);
    // stage Q (hi/lo) into smem with plain stores
#pragma unroll
    for (int t = 0; t < 4; t++) {
        int fi = tid + t * 256, r = fi >> 3, c8 = (fi & 7) * 8;
        size_t g = (size_t)(rowbase + q0 + r) * EMB + h * HDIM + c8;
        uint32_t off = (uint32_t)(r * GP + c8) * 2;
        *(uint4*)(smem + FQH + off) = *(const uint4*)(g_qh + g);
        *(uint4*)(smem + FQL + off) = *(const uint4*)(g_ql + g);
    }
    CP_WAIT0();
    __syncthreads();

    // Q fragments held in registers for all 32 tiles
    uint32_t qh[4][4], ql[4][4];
#pragma unroll
    for (int kb = 0; kb < 4; kb++) {
        uint32_t ro = (uint32_t)((wr0 + lrA) * GP + kb * 16 + lcA) * 2;
        ldm4(qh[kb], sb + FQH + ro);
        ldm4(ql[kb], sb + FQL + ro);
    }

    float o[8][4];
#pragma unroll
    for (int a = 0; a < 8; a++)
#pragma unroll
        for (int d = 0; d < 4; d++) o[a][d] = 0.f;
    float l0 = 0.f, l1 = 0.f;

    // per-thread constant offset into the staged bias window
    const int off0 = 127 + (lane & 3) * 2 - wr0 - (lane >> 2);

    int cur = 0;
    for (int kt = 0; kt < 32; kt++) {
        if (kt < 31) loadkv(kt + 1, cur ^ 1);
        const uint32_t kvb = sb + FKV0 + cur * FSTG;
        const float* stab = (const float*)(smem + FTAB + cur * 768);

        // ---- S = Q K^T (3-term split) ----
        float sc[8][4];
#pragma unroll
        for (int a = 0; a < 8; a++)
#pragma unroll
            for (int d = 0; d < 4; d++) sc[a][d] = 0.f;
#pragma unroll
        for (int kb = 0; kb < 4; kb++) {
#pragma unroll
            for (int nb2 = 0; nb2 < 4; nb2++) {
                uint32_t bh[4], bl[4];
                uint32_t ro = (uint32_t)((nb2 * 16 + lrB) * GP + kb * 16 + lcB) * 2;
                ldm4(bh, kvb + FKH + ro);
                ldm4(bl, kvb + FKL + ro);
                mma16816(sc[nb2 * 2 + 0], qh[kb], bh);
                mma16816(sc[nb2 * 2 + 0], qh[kb], bl);
                mma16816(sc[nb2 * 2 + 0], ql[kb], bh);
                mma16816(sc[nb2 * 2 + 1], qh[kb], bh + 2);
                mma16816(sc[nb2 * 2 + 1], qh[kb], bl + 2);
                mma16816(sc[nb2 * 2 + 1], ql[kb], bh + 2);
            }
        }

        // ---- softmax (fixed shift), bias from smem window ----
        uint32_t pa[4][4], pl[4][4];
#pragma unroll
        for (int nb = 0; nb < 8; nb++) {
            int j = off0 + nb * 8;
            float p00 = __expf(sc[nb][0] + stab[j]);
            float p01 = __expf(sc[nb][1] + stab[j + 1]);
            float p10 = __expf(sc[nb][2] + stab[j - 8]);
            float p11 = __expf(sc[nb][3] + stab[j - 7]);
            l0 += p00 + p01;
            l1 += p10 + p11;
            uint32_t u0 = pack_bf16x2(p00, p01);
            uint32_t u1 = pack_bf16x2(p10, p11);
            int kb = nb >> 1, sl = (nb & 1) * 2;
            pa[kb][sl + 0] = u0;
            pa[kb][sl + 1] = u1;
            pl[kb][sl + 0] = pack_bf16x2(p00 - lo_f32(u0), p01 - hi_f32(u0));
            pl[kb][sl + 1] = pack_bf16x2(p10 - lo_f32(u1), p11 - hi_f32(u1));
        }

        // ---- O += P V (3-term split) ----
#pragma unroll
        for (int kb = 0; kb < 4; kb++) {
#pragma unroll
            for (int nb2 = 0; nb2 < 4; nb2++) {
                uint32_t vh[4], vl[4];
                uint32_t ro = (uint32_t)((kb * 16 + lrA) * GP + nb2 * 16 + lcA) * 2;
                ldm4t(vh, kvb + FVH + ro);
                ldm4t(vl, kvb + FVL + ro);
                mma16816(o[nb2 * 2 + 0], pa[kb], vh);
                mma16816(o[nb2 * 2 + 0], pa[kb], vl);
                mma16816(o[nb2 * 2 + 0], pl[kb], vh);
                mma16816(o[nb2 * 2 + 1], pa[kb], vh + 2);
                mma16816(o[nb2 * 2 + 1], pa[kb], vl + 2);
                mma16816(o[nb2 * 2 + 1], pl[kb], vh + 2);
            }
        }
        if (kt < 31) CP_WAIT0();
        __syncthreads();
        cur ^= 1;
    }

    // reduce row sums over the 4-lane quads, normalize, store split bf16
    l0 += __shfl_xor_sync(0xffffffffu, l0, 1);
    l0 += __shfl_xor_sync(0xffffffffu, l0, 2);
    l1 += __shfl_xor_sync(0xffffffffu, l1, 1);
    l1 += __shfl_xor_sync(0xffffffffu, l1, 2);
    float inv0 = 1.0f / l0, inv1 = 1.0f / l1;
    const int rg = rowbase + q0 + wr0 + (lane >> 2);
#pragma unroll
    for (int nb = 0; nb < 8; nb++) {
        int cg = h * HDIM + nb * 8 + (lane & 3) * 2;
        split_store2(g_aoh, g_aol, (size_t)rg * EMB + cg,
                     o[nb][0] * inv0, o[nb][1] * inv0);
        split_store2(g_aoh, g_aol, (size_t)(rg + 8) * EMB + cg,
                     o[nb][2] * inv1, o[nb][3] * inv1);
    }
}

// ---------------- launch ----------------------------------------------------
extern "C" void kernel_launch(void* const* d_in, const int* in_sizes, int n_in,
                              void* d_out, int out_size) {
    (void)in_sizes; (void)n_in; (void)out_size;
    const float* x   = (const float*)d_in[0];
    const float* Wq  = (const float*)d_in[1];
    const float* Wk  = (const float*)d_in[2];
    const float* Wv  = (const float*)d_in[3];
    const float* Wo  = (const float*)d_in[4];
    const float* rel = (const float*)d_in[5];

    float* out  = (float*)d_out;
    float* bias = out + OUT_ELEMS;

    build_tab_kernel<<<(HEADS * TABW + 255) / 256, 256>>>(rel);
    wsplit_kernel<<<dim3(32, 32, 4), dim3(32, 8)>>>(Wq, Wk, Wv, Wo);
    xsplit_kernel<<<ROWS_TOT * EMB / 4 / 256, 256>>>(x);

    cudaFuncSetAttribute(qkv_mma_kernel, cudaFuncAttributeMaxDynamicSharedMemorySize, GEMM_SMEM);
    cudaFuncSetAttribute(out_mma_kernel, cudaFuncAttributeMaxDynamicSharedMemorySize, GEMM_SMEM);
    cudaFuncSetAttribute(flash_kernel, cudaFuncAttributeMaxDynamicSharedMemorySize, SMEM_FLASH);

    qkv_mma_kernel<<<dim3(8, 32, 3), 256, GEMM_SMEM>>>(bias);
    flash_kernel<<<dim3(SLEN / 128, HEADS, BATCH), 256, SMEM_FLASH>>>();
    out_mma_kernel<<<dim3(8, 32), 256, GEMM_SMEM>>>(out);
}

// round 13
// speedup vs baseline: 1.1680x; 1.0542x over previous
#include <cuda_runtime.h>
#include <cuda_bf16.h>
#include <math.h>
#include <stdint.h>

#define BATCH 2
#define SLEN  2048
#define HEADS 16
#define HDIM  64
#define EMB   1024
#define ROWS_TOT (BATCH*SLEN)        /* 4096 */
#define OUT_ELEMS (ROWS_TOT*EMB)
#define TABW  4095
#define MSHIFT 20.0f
#define GP 72                         /* flash smem row pitch in bf16 elems */

// ---------------- scratch (device globals) ---------------------------------
__device__ __nv_bfloat16 g_xh[ROWS_TOT*EMB],  g_xl[ROWS_TOT*EMB];
__device__ __nv_bfloat16 g_whi[4*EMB*EMB],    g_wlo[4*EMB*EMB];   // [n][k]
__device__ __nv_bfloat16 g_qh[ROWS_TOT*EMB],  g_ql[ROWS_TOT*EMB];
__device__ __nv_bfloat16 g_kh[ROWS_TOT*EMB],  g_kl[ROWS_TOT*EMB];
__device__ __nv_bfloat16 g_vh[ROWS_TOT*EMB],  g_vl[ROWS_TOT*EMB];
__device__ __nv_bfloat16 g_aoh[ROWS_TOT*EMB], g_aol[ROWS_TOT*EMB];
__device__ float g_tab[HEADS*TABW];
__device__ float g_tab2[HEADS*TABW];

// ---------------- helpers ---------------------------------------------------
static __device__ __forceinline__ uint32_t smem_u32(const void* p) {
    return (uint32_t)__cvta_generic_to_shared(p);
}
static __device__ __forceinline__ void cpa16(uint32_t s, const void* g) {
    asm volatile("cp.async.cg.shared.global [%0], [%1], 16;" :: "r"(s), "l"(g));
}
static __device__ __forceinline__ void cpa4(uint32_t s, const void* g) {
    asm volatile("cp.async.ca.shared.global [%0], [%1], 4;" :: "r"(s), "l"(g));
}
#define CP_COMMIT() asm volatile("cp.async.commit_group;" ::: "memory")
#define CP_WAIT0()  asm volatile("cp.async.wait_group 0;" ::: "memory")
#define CP_WAIT1()  asm volatile("cp.async.wait_group 1;" ::: "memory")
static __device__ __forceinline__ void ldm4(uint32_t* r, uint32_t a) {
    asm volatile("ldmatrix.sync.aligned.m8n8.x4.shared.b16 {%0,%1,%2,%3}, [%4];"
        : "=r"(r[0]), "=r"(r[1]), "=r"(r[2]), "=r"(r[3]) : "r"(a));
}
static __device__ __forceinline__ void ldm4t(uint32_t* r, uint32_t a) {
    asm volatile("ldmatrix.sync.aligned.m8n8.x4.trans.shared.b16 {%0,%1,%2,%3}, [%4];"
        : "=r"(r[0]), "=r"(r[1]), "=r"(r[2]), "=r"(r[3]) : "r"(a));
}
static __device__ __forceinline__ void mma16816(float* c, const uint32_t* a, const uint32_t* b) {
    asm volatile(
        "mma.sync.aligned.m16n8k16.row.col.f32.bf16.bf16.f32 "
        "{%0,%1,%2,%3}, {%4,%5,%6,%7}, {%8,%9}, {%0,%1,%2,%3};"
        : "+f"(c[0]), "+f"(c[1]), "+f"(c[2]), "+f"(c[3])
        : "r"(a[0]), "r"(a[1]), "r"(a[2]), "r"(a[3]), "r"(b[0]), "r"(b[1]));
}
static __device__ __forceinline__ uint32_t pack_bf16x2(float lo, float hi) {
    __nv_bfloat162 t = __floats2bfloat162_rn(lo, hi);
    return *reinterpret_cast<uint32_t*>(&t);
}
static __device__ __forceinline__ float lo_f32(uint32_t u) { return __uint_as_float(u << 16); }
static __device__ __forceinline__ float hi_f32(uint32_t u) { return __uint_as_float(u & 0xffff0000u); }
static __device__ __forceinline__ void split_store2(__nv_bfloat16* H, __nv_bfloat16* L,
                                                    size_t idx, float v0, float v1) {
    __nv_bfloat162 hh = __floats2bfloat162_rn(v0, v1);
    __nv_bfloat162 ll = __floats2bfloat162_rn(v0 - __bfloat162float(hh.x),
                                              v1 - __bfloat162float(hh.y));
    *reinterpret_cast<__nv_bfloat162*>(H + idx) = hh;
    *reinterpret_cast<__nv_bfloat162*>(L + idx) = ll;
}

// ---------------- T5 bucket + bias table ------------------------------------
__device__ __forceinline__ int rel_bucket(int d) {
    int base = (d > 0) ? 16 : 0;
    int rp = abs(d);
    if (rp < 8) return base + rp;
    double v = log((double)rp / 8.0) / log(16.0) * 8.0;
    int b = (int)(v + 1e-6);
    if (b > 7) b = 7;
    return base + 8 + b;
}
__global__ void build_tab_kernel(const float* __restrict__ rel) {
    int idx = blockIdx.x * blockDim.x + threadIdx.x;
    if (idx >= HEADS * TABW) return;
    int h = idx / TABW, dd = idx % TABW;
    float b = rel[rel_bucket(dd - 2047) * HEADS + h];
    g_tab[h * TABW + dd]  = b;
    g_tab2[h * TABW + dd] = b - MSHIFT;
}

// ---------------- input / weight splitting ----------------------------------
__global__ void xsplit_kernel(const float* __restrict__ x) {
    int idx = blockIdx.x * blockDim.x + threadIdx.x;   // float4 id
    float4 v = reinterpret_cast<const float4*>(x)[idx];
    __nv_bfloat162 h0 = __floats2bfloat162_rn(v.x, v.y);
    __nv_bfloat162 h1 = __floats2bfloat162_rn(v.z, v.w);
    __nv_bfloat162 l0 = __floats2bfloat162_rn(v.x - __bfloat162float(h0.x),
                                              v.y - __bfloat162float(h0.y));
    __nv_bfloat162 l1 = __floats2bfloat162_rn(v.z - __bfloat162float(h1.x),
                                              v.w - __bfloat162float(h1.y));
    reinterpret_cast<__nv_bfloat162*>(g_xh)[idx * 2]     = h0;
    reinterpret_cast<__nv_bfloat162*>(g_xh)[idx * 2 + 1] = h1;
    reinterpret_cast<__nv_bfloat162*>(g_xl)[idx * 2]     = l0;
    reinterpret_cast<__nv_bfloat162*>(g_xl)[idx * 2 + 1] = l1;
}
// W[k][n] -> Wt[n][k] hi/lo. grid (32,32,4), block (32,8)
__global__ __launch_bounds__(256) void wsplit_kernel(const float* __restrict__ W0,
                                                     const float* __restrict__ W1,
                                                     const float* __restrict__ W2,
                                                     const float* __restrict__ W3) {
    __shared__ float t[32][33];
    const float* W = (blockIdx.z == 0) ? W0 : (blockIdx.z == 1) ? W1
                   : (blockIdx.z == 2) ? W2 : W3;
    int n0 = blockIdx.x * 32, k0 = blockIdx.y * 32;
#pragma unroll
    for (int i = threadIdx.y; i < 32; i += 8)
        t[i][threadIdx.x] = W[(size_t)(k0 + i) * EMB + n0 + threadIdx.x];
    __syncthreads();
    __nv_bfloat16* hi = g_whi + (size_t)blockIdx.z * EMB * EMB;
    __nv_bfloat16* lo = g_wlo + (size_t)blockIdx.z * EMB * EMB;
#pragma unroll
    for (int i = threadIdx.y; i < 32; i += 8) {
        float v = t[threadIdx.x][i];
        __nv_bfloat16 h = __float2bfloat16(v);
        size_t o = (size_t)(n0 + i) * EMB + k0 + threadIdx.x;
        hi[o] = h;
        lo[o] = __float2bfloat16(v - __bfloat162float(h));
    }
}

// ---------------- tensor-core GEMM: XOR-swizzled, 3-stage cp.async ----------
// 64B rows (KC=32 bf16); chunk swizzle c^( (r>>1)&3 ) is ldsm conflict-free.
#define KC 32
#define GT 8192                        /* one 128x32 bf16 tile */
#define GAH 0
#define GAL GT
#define GBH (2*GT)
#define GBL (3*GT)
#define GSTAGEB (4*GT)                 /* 32768 */
#define GEMM_SMEM (3*GSTAGEB)          /* 98304 */

__device__ __forceinline__ void gemm_body(
    const __nv_bfloat16* __restrict__ Ah, const __nv_bfloat16* __restrict__ Al,
    const __nv_bfloat16* __restrict__ Bh, const __nv_bfloat16* __restrict__ Bl,
    __nv_bfloat16* __restrict__ Oh, __nv_bfloat16* __restrict__ Ol,
    float* __restrict__ Of)
{
    extern __shared__ __align__(16) char smem[];
    const uint32_t sb = smem_u32(smem);
    const int tid = threadIdx.x, lane = tid & 31, wid = tid >> 5;
    const int wm = wid >> 2, wn = wid & 3;
    const int row0 = blockIdx.y * 128, col0 = blockIdx.x * 128;

    const int lrA = (lane & 7) + ((lane >> 3) & 1) * 8;   // A-frag row in 16
    const int lrB = (lane & 7) + ((lane >> 4) << 3);      // B-frag row in 16
    const int swA = (lrA >> 1) & 3, ccA = lane >> 4;        // swizzle consts
    const int swB = (lrB >> 1) & 3, ccB = (lane >> 3) & 1;

    float c[4][4][4];
#pragma unroll
    for (int a = 0; a < 4; a++)
#pragma unroll
        for (int b = 0; b < 4; b++)
#pragma unroll
            for (int d = 0; d < 4; d++) c[a][b][d] = 0.f;

    auto loadch = [&](int k0, int s) {
        uint32_t b = sb + s * GSTAGEB;
#pragma unroll
        for (int t = 0; t < 2; t++) {
            int fi = tid + t * 256;
            int r = fi >> 2, ck = fi & 3;
            uint32_t so = (uint32_t)(r * 64 + ((ck ^ ((r >> 1) & 3)) << 4));
            size_t ga = (size_t)(row0 + r) * EMB + k0 + ck * 8;
            size_t gb = (size_t)(col0 + r) * EMB + k0 + ck * 8;
            cpa16(b + GAH + so, Ah + ga);
            cpa16(b + GAL + so, Al + ga);
            cpa16(b + GBH + so, Bh + gb);
            cpa16(b + GBL + so, Bl + gb);
        }
        CP_COMMIT();
    };

    loadch(0, 0);
    loadch(KC, 1);
    CP_WAIT1();              // chunk 0 resident
    __syncthreads();

    for (int ch = 0; ch < 32; ch++) {
        if (ch + 2 < 32) loadch((ch + 2) * KC, (ch + 2) % 3);
        const uint32_t base = sb + (ch % 3) * GSTAGEB;
#pragma unroll
        for (int kk = 0; kk < 2; kk++) {
            uint32_t ah[4][4], al_[4][4];
#pragma unroll
            for (int mi = 0; mi < 4; mi++) {
                uint32_t ro = (uint32_t)((wm * 64 + mi * 16 + lrA) * 64
                                         + (((kk * 2 + ccA) ^ swA) << 4));
                ldm4(ah[mi],  base + GAH + ro);
                ldm4(al_[mi], base + GAL + ro);
            }
#pragma unroll
            for (int nj2 = 0; nj2 < 2; nj2++) {
                uint32_t bh[4], bl[4];
                uint32_t ro = (uint32_t)((wn * 32 + nj2 * 16 + lrB) * 64
                                         + (((kk * 2 + ccB) ^ swB) << 4));
                ldm4(bh, base + GBH + ro);
                ldm4(bl, base + GBL + ro);
#pragma unroll
                for (int mi = 0; mi < 4; mi++) {
                    mma16816(c[mi][nj2 * 2 + 0], ah[mi],  bh);
                    mma16816(c[mi][nj2 * 2 + 0], ah[mi],  bl);
                    mma16816(c[mi][nj2 * 2 + 0], al_[mi], bh);
                    mma16816(c[mi][nj2 * 2 + 1], ah[mi],  bh + 2);
                    mma16816(c[mi][nj2 * 2 + 1], ah[mi],  bl + 2);
                    mma16816(c[mi][nj2 * 2 + 1], al_[mi], bh + 2);
                }
            }
        }
        if (ch + 1 < 32) {
            if (ch + 2 < 32) { CP_WAIT1(); } else { CP_WAIT0(); }
            __syncthreads();
        }
    }

#pragma unroll
    for (int mi = 0; mi < 4; mi++)
#pragma unroll
        for (int nj = 0; nj < 4; nj++) {
            int rg = row0 + wm * 64 + mi * 16 + (lane >> 2);
            int cg = col0 + wn * 32 + nj * 8 + (lane & 3) * 2;
            size_t i0 = (size_t)rg * EMB + cg, i1 = (size_t)(rg + 8) * EMB + cg;
            if (Of) {
                *(float2*)(Of + i0) = make_float2(c[mi][nj][0], c[mi][nj][1]);
                *(float2*)(Of + i1) = make_float2(c[mi][nj][2], c[mi][nj][3]);
            } else {
                split_store2(Oh, Ol, i0, c[mi][nj][0], c[mi][nj][1]);
                split_store2(Oh, Ol, i1, c[mi][nj][2], c[mi][nj][3]);
            }
        }
}

// qkv GEMM + fire-and-forget position_bias stores in the prologue.
__global__ __launch_bounds__(256, 2) void qkv_mma_kernel(float* __restrict__ bias) {
    const int tid = threadIdx.x;
    const int cta = ((int)blockIdx.z << 8) + ((int)blockIdx.y << 3) + (int)blockIdx.x;
    for (uint32_t i = (uint32_t)cta * 256 + tid; i < (1u << 24); i += 768u * 256u) {
        uint32_t k4 = i & 511, q = (i >> 9) & 2047, h = i >> 20;
        int d = (int)(k4 << 2) - (int)q + 2047;
        const float* t = g_tab + h * TABW + d;
        float4 v = make_float4(__ldg(t), __ldg(t + 1), __ldg(t + 2), __ldg(t + 3));
        __stcs(reinterpret_cast<float4*>(bias) + i, v);
    }

    int z = blockIdx.z;
    __nv_bfloat16* Oh = (z == 0) ? g_qh : (z == 1) ? g_kh : g_vh;
    __nv_bfloat16* Ol = (z == 0) ? g_ql : (z == 1) ? g_kl : g_vl;
    gemm_body(g_xh, g_xl, g_whi + (size_t)z * EMB * EMB, g_wlo + (size_t)z * EMB * EMB,
              Oh, Ol, nullptr);
}
__global__ __launch_bounds__(256, 2) void out_mma_kernel(float* __restrict__ out) {
    gemm_body(g_aoh, g_aol, g_whi + (size_t)3 * EMB * EMB, g_wlo + (size_t)3 * EMB * EMB,
              nullptr, nullptr, out);
}

// ---------------- flash attention (3-term PV, cp.async, 2 CTAs/SM) ----------
#define FQH  0
#define FQL  18432
#define FKV0 36864
#define FSTG 36864
#define FKH  0
#define FKL  9216
#define FVH  18432
#define FVL  27648
#define FTAB (FKV0 + 2*FSTG)          /* bias windows: 2 stages x 192 floats */
#define SMEM_FLASH (FTAB + 2*192*4)   /* 112128 */

__global__ __launch_bounds__(256, 2) void flash_kernel() {
    extern __shared__ __align__(16) char smem[];
    const uint32_t sb = smem_u32(smem);
    const int tid = threadIdx.x, lane = tid & 31, wid = tid >> 5;
    const int wr0 = wid * 16;
    const int q0 = blockIdx.x * 128, h = blockIdx.y, rowbase = blockIdx.z * SLEN;
    const float* tabh = g_tab2 + h * TABW;

    const int lrA = (lane & 7) + ((lane >> 3) & 1) * 8;
    const int lcA = (lane >> 4) * 8;
    const int lrB = (lane & 7) + ((lane >> 4) << 3);
    const int lcB = ((lane >> 3) & 1) * 8;

    auto loadkv = [&](int kt, int s) {
        const int k0 = kt * 64;
        uint32_t b = sb + FKV0 + s * FSTG;
#pragma unroll
        for (int t = 0; t < 2; t++) {
            int fi = tid + t * 256;
            int r = fi >> 3, c8 = (fi & 7) * 8;
            uint32_t so = (uint32_t)(r * GP + c8) * 2;
            size_t g = (size_t)(rowbase + k0 + r) * EMB + h * HDIM + c8;
            cpa16(b + FKH + so, g_kh + g);
            cpa16(b + FKL + so, g_kl + g);
            cpa16(b + FVH + so, g_vh + g);
            cpa16(b + FVL + so, g_vl + g);
        }
        if (tid < 192) {     // stage this tile's 192-float bias window
            int idx = (k0 - q0 + 1920) + tid;
            if (idx > TABW - 1) idx = TABW - 1;
            cpa4(sb + FTAB + s * 768 + tid * 4, tabh + idx);
        }
        CP_COMMIT();
    };

    loadkv(0, 0);
    // stage Q (hi/lo) into smem with plain stores
#pragma unroll
    for (int t = 0; t < 4; t++) {
        int fi = tid + t * 256, r = fi >> 3, c8 = (fi & 7) * 8;
        size_t g = (size_t)(rowbase + q0 + r) * EMB + h * HDIM + c8;
        uint32_t off = (uint32_t)(r * GP + c8) * 2;
        *(uint4*)(smem + FQH + off) = *(const uint4*)(g_qh + g);
        *(uint4*)(smem + FQL + off) = *(const uint4*)(g_ql + g);
    }
    CP_WAIT0();
    __syncthreads();

    // Q fragments held in registers for all 32 tiles
    uint32_t qh[4][4], ql[4][4];
#pragma unroll
    for (int kb = 0; kb < 4; kb++) {
        uint32_t ro = (uint32_t)((wr0 + lrA) * GP + kb * 16 + lcA) * 2;
        ldm4(qh[kb], sb + FQH + ro);
        ldm4(ql[kb], sb + FQL + ro);
    }

    float o[8][4];
#pragma unroll
    for (int a = 0; a < 8; a++)
#pragma unroll
        for (int d = 0; d < 4; d++) o[a][d] = 0.f;
    float l0 = 0.f, l1 = 0.f;

    // per-thread constant offset into the staged bias window
    const int off0 = 127 + (lane & 3) * 2 - wr0 - (lane >> 2);

    int cur = 0;
    for (int kt = 0; kt < 32; kt++) {
        if (kt < 31) loadkv(kt + 1, cur ^ 1);
        const uint32_t kvb = sb + FKV0 + cur * FSTG;
        const float* stab = (const float*)(smem + FTAB + cur * 768);

        // ---- S = Q K^T (3-term split) ----
        float sc[8][4];
#pragma unroll
        for (int a = 0; a < 8; a++)
#pragma unroll
            for (int d = 0; d < 4; d++) sc[a][d] = 0.f;
#pragma unroll
        for (int kb = 0; kb < 4; kb++) {
#pragma unroll
            for (int nb2 = 0; nb2 < 4; nb2++) {
                uint32_t bh[4], bl[4];
                uint32_t ro = (uint32_t)((nb2 * 16 + lrB) * GP + kb * 16 + lcB) * 2;
                ldm4(bh, kvb + FKH + ro);
                ldm4(bl, kvb + FKL + ro);
                mma16816(sc[nb2 * 2 + 0], qh[kb], bh);
                mma16816(sc[nb2 * 2 + 0], qh[kb], bl);
                mma16816(sc[nb2 * 2 + 0], ql[kb], bh);
                mma16816(sc[nb2 * 2 + 1], qh[kb], bh + 2);
                mma16816(sc[nb2 * 2 + 1], qh[kb], bl + 2);
                mma16816(sc[nb2 * 2 + 1], ql[kb], bh + 2);
            }
        }

        // ---- softmax (fixed shift), bias from smem window ----
        uint32_t pa[4][4], pl[4][4];
#pragma unroll
        for (int nb = 0; nb < 8; nb++) {
            int j = off0 + nb * 8;
            float p00 = __expf(sc[nb][0] + stab[j]);
            float p01 = __expf(sc[nb][1] + stab[j + 1]);
            float p10 = __expf(sc[nb][2] + stab[j - 8]);
            float p11 = __expf(sc[nb][3] + stab[j - 7]);
            l0 += p00 + p01;
            l1 += p10 + p11;
            uint32_t u0 = pack_bf16x2(p00, p01);
            uint32_t u1 = pack_bf16x2(p10, p11);
            int kb = nb >> 1, sl = (nb & 1) * 2;
            pa[kb][sl + 0] = u0;
            pa[kb][sl + 1] = u1;
            pl[kb][sl + 0] = pack_bf16x2(p00 - lo_f32(u0), p01 - hi_f32(u0));
            pl[kb][sl + 1] = pack_bf16x2(p10 - lo_f32(u1), p11 - hi_f32(u1));
        }

        // ---- O += P V (3-term split) ----
#pragma unroll
        for (int kb = 0; kb < 4; kb++) {
#pragma unroll
            for (int nb2 = 0; nb2 < 4; nb2++) {
                uint32_t vh[4], vl[4];
                uint32_t ro = (uint32_t)((kb * 16 + lrA) * GP + nb2 * 16 + lcA) * 2;
                ldm4t(vh, kvb + FVH + ro);
                ldm4t(vl, kvb + FVL + ro);
                mma16816(o[nb2 * 2 + 0], pa[kb], vh);
                mma16816(o[nb2 * 2 + 0], pa[kb], vl);
                mma16816(o[nb2 * 2 + 0], pl[kb], vh);
                mma16816(o[nb2 * 2 + 1], pa[kb], vh + 2);
                mma16816(o[nb2 * 2 + 1], pa[kb], vl + 2);
                mma16816(o[nb2 * 2 + 1], pl[kb], vh + 2);
            }
        }
        if (kt < 31) CP_WAIT0();
        __syncthreads();
        cur ^= 1;
    }

    // reduce row sums over the 4-lane quads, normalize, store split bf16
    l0 += __shfl_xor_sync(0xffffffffu, l0, 1);
    l0 += __shfl_xor_sync(0xffffffffu, l0, 2);
    l1 += __shfl_xor_sync(0xffffffffu, l1, 1);
    l1 += __shfl_xor_sync(0xffffffffu, l1, 2);
    float inv0 = 1.0f / l0, inv1 = 1.0f / l1;
    const int rg = rowbase + q0 + wr0 + (lane >> 2);
#pragma unroll
    for (int nb = 0; nb < 8; nb++) {
        int cg = h * HDIM + nb * 8 + (lane & 3) * 2;
        split_store2(g_aoh, g_aol, (size_t)rg * EMB + cg,
                     o[nb][0] * inv0, o[nb][1] * inv0);
        split_store2(g_aoh, g_aol, (size_t)(rg + 8) * EMB + cg,
                     o[nb][2] * inv1, o[nb][3] * inv1);
    }
}

// ---------------- launch ----------------------------------------------------
extern "C" void kernel_launch(void* const* d_in, const int* in_sizes, int n_in,
                              void* d_out, int out_size) {
    (void)in_sizes; (void)n_in; (void)out_size;
    const float* x   = (const float*)d_in[0];
    const float* Wq  = (const float*)d_in[1];
    const float* Wk  = (const float*)d_in[2];
    const float* Wv  = (const float*)d_in[3];
    const float* Wo  = (const float*)d_in[4];
    const float* rel = (const float*)d_in[5];

    float* out  = (float*)d_out;
    float* bias = out + OUT_ELEMS;

    build_tab_kernel<<<(HEADS * TABW + 255) / 256, 256>>>(rel);
    wsplit_kernel<<<dim3(32, 32, 4), dim3(32, 8)>>>(Wq, Wk, Wv, Wo);
    xsplit_kernel<<<ROWS_TOT * EMB / 4 / 256, 256>>>(x);

    cudaFuncSetAttribute(qkv_mma_kernel, cudaFuncAttributeMaxDynamicSharedMemorySize, GEMM_SMEM);
    cudaFuncSetAttribute(out_mma_kernel, cudaFuncAttributeMaxDynamicSharedMemorySize, GEMM_SMEM);
    cudaFuncSetAttribute(flash_kernel, cudaFuncAttributeMaxDynamicSharedMemorySize, SMEM_FLASH);

    qkv_mma_kernel<<<dim3(8, 32, 3), 256, GEMM_SMEM>>>(bias);
    flash_kernel<<<dim3(SLEN / 128, HEADS, BATCH), 256, SMEM_FLASH>>>();
    out_mma_kernel<<<dim3(8, 32), 256, GEMM_SMEM>>>(out);
}

// round 15
// speedup vs baseline: 1.2219x; 1.0462x over previous
#include <cuda_runtime.h>
#include <cuda_bf16.h>
#include <math.h>
#include <stdint.h>

#define BATCH 2
#define SLEN  2048
#define HEADS 16
#define HDIM  64
#define EMB   1024
#define ROWS_TOT (BATCH*SLEN)        /* 4096 */
#define OUT_ELEMS (ROWS_TOT*EMB)
#define TABW  4095
#define MSHIFT 20.0f
#define GP 72                         /* flash smem row pitch in bf16 elems */

// ---------------- scratch (device globals) ---------------------------------
__device__ __nv_bfloat16 g_xh[ROWS_TOT*EMB],  g_xl[ROWS_TOT*EMB];
__device__ __nv_bfloat16 g_whi[4*EMB*EMB],    g_wlo[4*EMB*EMB];   // [n][k]
__device__ __nv_bfloat16 g_qh[ROWS_TOT*EMB],  g_ql[ROWS_TOT*EMB];
__device__ __nv_bfloat16 g_kh[ROWS_TOT*EMB],  g_kl[ROWS_TOT*EMB];
__device__ __nv_bfloat16 g_vh[ROWS_TOT*EMB],  g_vl[ROWS_TOT*EMB];
__device__ __nv_bfloat16 g_aoh[ROWS_TOT*EMB], g_aol[ROWS_TOT*EMB];
__device__ float g_tab[HEADS*TABW];
__device__ float g_tab2[HEADS*TABW];

// ---------------- helpers ---------------------------------------------------
static __device__ __forceinline__ uint32_t smem_u32(const void* p) {
    return (uint32_t)__cvta_generic_to_shared(p);
}
static __device__ __forceinline__ void cpa16(uint32_t s, const void* g) {
    asm volatile("cp.async.cg.shared.global [%0], [%1], 16;" :: "r"(s), "l"(g));
}
static __device__ __forceinline__ void cpa4(uint32_t s, const void* g) {
    asm volatile("cp.async.ca.shared.global [%0], [%1], 4;" :: "r"(s), "l"(g));
}
#define CP_COMMIT() asm volatile("cp.async.commit_group;" ::: "memory")
#define CP_WAIT0()  asm volatile("cp.async.wait_group 0;" ::: "memory")
#define CP_WAIT1()  asm volatile("cp.async.wait_group 1;" ::: "memory")
static __device__ __forceinline__ void ldm4(uint32_t* r, uint32_t a) {
    asm volatile("ldmatrix.sync.aligned.m8n8.x4.shared.b16 {%0,%1,%2,%3}, [%4];"
        : "=r"(r[0]), "=r"(r[1]), "=r"(r[2]), "=r"(r[3]) : "r"(a));
}
static __device__ __forceinline__ void ldm4t(uint32_t* r, uint32_t a) {
    asm volatile("ldmatrix.sync.aligned.m8n8.x4.trans.shared.b16 {%0,%1,%2,%3}, [%4];"
        : "=r"(r[0]), "=r"(r[1]), "=r"(r[2]), "=r"(r[3]) : "r"(a));
}
static __device__ __forceinline__ void mma16816(float* c, const uint32_t* a, const uint32_t* b) {
    asm volatile(
        "mma.sync.aligned.m16n8k16.row.col.f32.bf16.bf16.f32 "
        "{%0,%1,%2,%3}, {%4,%5,%6,%7}, {%8,%9}, {%0,%1,%2,%3};"
        : "+f"(c[0]), "+f"(c[1]), "+f"(c[2]), "+f"(c[3])
        : "r"(a[0]), "r"(a[1]), "r"(a[2]), "r"(a[3]), "r"(b[0]), "r"(b[1]));
}
static __device__ __forceinline__ uint32_t pack_bf16x2(float lo, float hi) {
    __nv_bfloat162 t = __floats2bfloat162_rn(lo, hi);
    return *reinterpret_cast<uint32_t*>(&t);
}
static __device__ __forceinline__ float lo_f32(uint32_t u) { return __uint_as_float(u << 16); }
static __device__ __forceinline__ float hi_f32(uint32_t u) { return __uint_as_float(u & 0xffff0000u); }
static __device__ __forceinline__ void split_store2(__nv_bfloat16* H, __nv_bfloat16* L,
                                                    size_t idx, float v0, float v1) {
    __nv_bfloat162 hh = __floats2bfloat162_rn(v0, v1);
    __nv_bfloat162 ll = __floats2bfloat162_rn(v0 - __bfloat162float(hh.x),
                                              v1 - __bfloat162float(hh.y));
    *reinterpret_cast<__nv_bfloat162*>(H + idx) = hh;
    *reinterpret_cast<__nv_bfloat162*>(L + idx) = ll;
}

// ---------------- T5 bucket -------------------------------------------------
__device__ __forceinline__ int rel_bucket(int d) {
    int base = (d > 0) ? 16 : 0;
    int rp = abs(d);
    if (rp < 8) return base + rp;
    double v = log((double)rp / 8.0) / log(16.0) * 8.0;
    int b = (int)(v + 1e-6);
    if (b > 7) b = 7;
    return base + 8 + b;
}

// ---------------- fused prep: bias table + x split + W split ----------------
// grid.x partition: [0,256) build_tab, [256,4352) xsplit, [4352,8448) wsplit
__global__ __launch_bounds__(256) void prep_kernel(const float* __restrict__ x,
                                                   const float* __restrict__ W0,
                                                   const float* __restrict__ W1,
                                                   const float* __restrict__ W2,
                                                   const float* __restrict__ W3,
                                                   const float* __restrict__ rel) {
    const int b = blockIdx.x, tid = threadIdx.x;
    if (b < 256) {
        int idx = b * 256 + tid;
        if (idx < HEADS * TABW) {
            int h = idx / TABW, dd = idx % TABW;
            float v = rel[rel_bucket(dd - 2047) * HEADS + h];
            g_tab[h * TABW + dd]  = v;
            g_tab2[h * TABW + dd] = v - MSHIFT;
        }
    } else if (b < 256 + 4096) {
        int idx = (b - 256) * 256 + tid;    // float4 id
        float4 v = reinterpret_cast<const float4*>(x)[idx];
        __nv_bfloat162 h0 = __floats2bfloat162_rn(v.x, v.y);
        __nv_bfloat162 h1 = __floats2bfloat162_rn(v.z, v.w);
        __nv_bfloat162 l0 = __floats2bfloat162_rn(v.x - __bfloat162float(h0.x),
                                                  v.y - __bfloat162float(h0.y));
        __nv_bfloat162 l1 = __floats2bfloat162_rn(v.z - __bfloat162float(h1.x),
                                                  v.w - __bfloat162float(h1.y));
        reinterpret_cast<__nv_bfloat162*>(g_xh)[idx * 2]     = h0;
        reinterpret_cast<__nv_bfloat162*>(g_xh)[idx * 2 + 1] = h1;
        reinterpret_cast<__nv_bfloat162*>(g_xl)[idx * 2]     = l0;
        reinterpret_cast<__nv_bfloat162*>(g_xl)[idx * 2 + 1] = l1;
    } else {
        __shared__ float t[32][33];
        int idx = b - 4352;
        int z = idx >> 10, ny = (idx >> 5) & 31, nx = idx & 31;
        const float* W = (z == 0) ? W0 : (z == 1) ? W1 : (z == 2) ? W2 : W3;
        int n0 = nx * 32, k0 = ny * 32;
        int tx = tid & 31, ty = tid >> 5;
#pragma unroll
        for (int i = ty; i < 32; i += 8)
            t[i][tx] = W[(size_t)(k0 + i) * EMB + n0 + tx];
        __syncthreads();
        __nv_bfloat16* hi = g_whi + (size_t)z * EMB * EMB;
        __nv_bfloat16* lo = g_wlo + (size_t)z * EMB * EMB;
#pragma unroll
        for (int i = ty; i < 32; i += 8) {
            float v = t[tx][i];
            __nv_bfloat16 h = __float2bfloat16(v);
            size_t o = (size_t)(n0 + i) * EMB + k0 + tx;
            hi[o] = h;
            lo[o] = __float2bfloat16(v - __bfloat162float(h));
        }
    }
}

// ---------------- tensor-core GEMM: XOR-swizzled, 3-stage cp.async ----------
// 64B rows (KC=32 bf16); chunk swizzle c^( (r>>1)&3 ) is ldsm conflict-free.
// Optional bias stream: 3 fire-and-forget float4 stores per chunk, overlapped
// with tensor work (total 32*3 >= 86 needed per thread across the grid).
#define KC 32
#define GT 8192                        /* one 128x32 bf16 tile */
#define GAH 0
#define GAL GT
#define GBH (2*GT)
#define GBL (3*GT)
#define GSTAGEB (4*GT)                 /* 32768 */
#define GEMM_SMEM (3*GSTAGEB)          /* 98304 */

__device__ __forceinline__ void gemm_body(
    const __nv_bfloat16* __restrict__ Ah, const __nv_bfloat16* __restrict__ Al,
    const __nv_bfloat16* __restrict__ Bh, const __nv_bfloat16* __restrict__ Bl,
    __nv_bfloat16* __restrict__ Oh, __nv_bfloat16* __restrict__ Ol,
    float* __restrict__ Of, float* __restrict__ bias)
{
    extern __shared__ __align__(16) char smem[];
    const uint32_t sb = smem_u32(smem);
    const int tid = threadIdx.x, lane = tid & 31, wid = tid >> 5;
    const int wm = wid >> 2, wn = wid & 3;
    const int row0 = blockIdx.y * 128, col0 = blockIdx.x * 128;

    const int lrA = (lane & 7) + ((lane >> 3) & 1) * 8;   // A-frag row in 16
    const int lrB = (lane & 7) + ((lane >> 4) << 3);      // B-frag row in 16
    const int swA = (lrA >> 1) & 3, ccA = lane >> 4;        // swizzle consts
    const int swB = (lrB >> 1) & 3, ccB = (lane >> 3) & 1;

    // bias stream base (qkv only)
    const uint32_t bbase = ((uint32_t)blockIdx.z * 256u + (uint32_t)blockIdx.y * 8u
                            + (uint32_t)blockIdx.x) * 256u + (uint32_t)tid;

    float c[4][4][4];
#pragma unroll
    for (int a = 0; a < 4; a++)
#pragma unroll
        for (int b = 0; b < 4; b++)
#pragma unroll
            for (int d = 0; d < 4; d++) c[a][b][d] = 0.f;

    auto loadch = [&](int k0, int s) {
        uint32_t b = sb + s * GSTAGEB;
#pragma unroll
        for (int t = 0; t < 2; t++) {
            int fi = tid + t * 256;
            int r = fi >> 2, ck = fi & 3;
            uint32_t so = (uint32_t)(r * 64 + ((ck ^ ((r >> 1) & 3)) << 4));
            size_t ga = (size_t)(row0 + r) * EMB + k0 + ck * 8;
            size_t gb = (size_t)(col0 + r) * EMB + k0 + ck * 8;
            cpa16(b + GAH + so, Ah + ga);
            cpa16(b + GAL + so, Al + ga);
            cpa16(b + GBH + so, Bh + gb);
            cpa16(b + GBL + so, Bl + gb);
        }
        CP_COMMIT();
    };

    loadch(0, 0);
    loadch(KC, 1);
    CP_WAIT1();              // chunk 0 resident
    __syncthreads();

    for (int ch = 0; ch < 32; ch++) {
        if (ch + 2 < 32) loadch((ch + 2) * KC, (ch + 2) % 3);

        // interleaved position_bias stores (fire-and-forget, overlaps MMAs)
        if (bias) {
#pragma unroll
            for (int j = 0; j < 3; j++) {
                uint32_t i = bbase + (uint32_t)(ch * 3 + j) * 196608u;
                if (i < 16777216u) {
                    uint32_t k4 = i & 511, q = (i >> 9) & 2047, h = i >> 20;
                    int d = (int)(k4 << 2) - (int)q + 2047;
                    const float* t = g_tab + h * TABW + d;
                    float4 v = make_float4(__ldg(t), __ldg(t + 1),
                                           __ldg(t + 2), __ldg(t + 3));
                    __stcs(reinterpret_cast<float4*>(bias) + i, v);
                }
            }
        }

        const uint32_t base = sb + (ch % 3) * GSTAGEB;
#pragma unroll
        for (int kk = 0; kk < 2; kk++) {
            uint32_t ah[4][4], al_[4][4];
#pragma unroll
            for (int mi = 0; mi < 4; mi++) {
                uint32_t ro = (uint32_t)((wm * 64 + mi * 16 + lrA) * 64
                                         + (((kk * 2 + ccA) ^ swA) << 4));
                ldm4(ah[mi],  base + GAH + ro);
                ldm4(al_[mi], base + GAL + ro);
            }
#pragma unroll
            for (int nj2 = 0; nj2 < 2; nj2++) {
                uint32_t bh[4], bl[4];
                uint32_t ro = (uint32_t)((wn * 32 + nj2 * 16 + lrB) * 64
                                         + (((kk * 2 + ccB) ^ swB) << 4));
                ldm4(bh, base + GBH + ro);
                ldm4(bl, base + GBL + ro);
#pragma unroll
                for (int mi = 0; mi < 4; mi++) {
                    mma16816(c[mi][nj2 * 2 + 0], ah[mi],  bh);
                    mma16816(c[mi][nj2 * 2 + 0], ah[mi],  bl);
                    mma16816(c[mi][nj2 * 2 + 0], al_[mi], bh);
                    mma16816(c[mi][nj2 * 2 + 1], ah[mi],  bh + 2);
                    mma16816(c[mi][nj2 * 2 + 1], ah[mi],  bl + 2);
                    mma16816(c[mi][nj2 * 2 + 1], al_[mi], bh + 2);
                }
            }
        }
        if (ch + 1 < 32) {
            if (ch + 2 < 32) { CP_WAIT1(); } else { CP_WAIT0(); }
            __syncthreads();
        }
    }

#pragma unroll
    for (int mi = 0; mi < 4; mi++)
#pragma unroll
        for (int nj = 0; nj < 4; nj++) {
            int rg = row0 + wm * 64 + mi * 16 + (lane >> 2);
            int cg = col0 + wn * 32 + nj * 8 + (lane & 3) * 2;
            size_t i0 = (size_t)rg * EMB + cg, i1 = (size_t)(rg + 8) * EMB + cg;
            if (Of) {
                *(float2*)(Of + i0) = make_float2(c[mi][nj][0], c[mi][nj][1]);
                *(float2*)(Of + i1) = make_float2(c[mi][nj][2], c[mi][nj][3]);
            } else {
                split_store2(Oh, Ol, i0, c[mi][nj][0], c[mi][nj][1]);
                split_store2(Oh, Ol, i1, c[mi][nj][2], c[mi][nj][3]);
            }
        }
}

__global__ __launch_bounds__(256, 2) void qkv_mma_kernel(float* __restrict__ bias) {
    int z = blockIdx.z;
    __nv_bfloat16* Oh = (z == 0) ? g_qh : (z == 1) ? g_kh : g_vh;
    __nv_bfloat16* Ol = (z == 0) ? g_ql : (z == 1) ? g_kl : g_vl;
    gemm_body(g_xh, g_xl, g_whi + (size_t)z * EMB * EMB, g_wlo + (size_t)z * EMB * EMB,
              Oh, Ol, nullptr, bias);
}
__global__ __launch_bounds__(256, 2) void out_mma_kernel(float* __restrict__ out) {
    gemm_body(g_aoh, g_aol, g_whi + (size_t)3 * EMB * EMB, g_wlo + (size_t)3 * EMB * EMB,
              nullptr, nullptr, out, nullptr);
}

// ---------------- flash attention (3-term PV, cp.async, 2 CTAs/SM) ----------
#define FQH  0
#define FQL  18432
#define FKV0 36864
#define FSTG 36864
#define FKH  0
#define FKL  9216
#define FVH  18432
#define FVL  27648
#define FTAB (FKV0 + 2*FSTG)          /* bias windows: 2 stages x 192 floats */
#define SMEM_FLASH (FTAB + 2*192*4)   /* 112128 */

__global__ __launch_bounds__(256, 2) void flash_kernel() {
    extern __shared__ __align__(16) char smem[];
    const uint32_t sb = smem_u32(smem);
    const int tid = threadIdx.x, lane = tid & 31, wid = tid >> 5;
    const int wr0 = wid * 16;
    const int q0 = blockIdx.x * 128, h = blockIdx.y, rowbase = blockIdx.z * SLEN;
    const float* tabh = g_tab2 + h * TABW;

    const int lrA = (lane & 7) + ((lane >> 3) & 1) * 8;
    const int lcA = (lane >> 4) * 8;
    const int lrB = (lane & 7) + ((lane >> 4) << 3);
    const int lcB = ((lane >> 3) & 1) * 8;

    auto loadkv = [&](int kt, int s) {
        const int k0 = kt * 64;
        uint32_t b = sb + FKV0 + s * FSTG;
#pragma unroll
        for (int t = 0; t < 2; t++) {
            int fi = tid + t * 256;
            int r = fi >> 3, c8 = (fi & 7) * 8;
            uint32_t so = (uint32_t)(r * GP + c8) * 2;
            size_t g = (size_t)(rowbase + k0 + r) * EMB + h * HDIM + c8;
            cpa16(b + FKH + so, g_kh + g);
            cpa16(b + FKL + so, g_kl + g);
            cpa16(b + FVH + so, g_vh + g);
            cpa16(b + FVL + so, g_vl + g);
        }
        if (tid < 192) {     // stage this tile's 192-float bias window
            int idx = (k0 - q0 + 1920) + tid;
            if (idx > TABW - 1) idx = TABW - 1;
            cpa4(sb + FTAB + s * 768 + tid * 4, tabh + idx);
        }
        CP_COMMIT();
    };

    loadkv(0, 0);
    // stage Q (hi/lo) into smem with plain stores
#pragma unroll
    for (int t = 0; t < 4; t++) {
        int fi = tid + t * 256, r = fi >> 3, c8 = (fi & 7) * 8;
        size_t g = (size_t)(rowbase + q0 + r) * EMB + h * HDIM + c8;
        uint32_t off = (uint32_t)(r * GP + c8) * 2;
        *(uint4*)(smem + FQH + off) = *(const uint4*)(g_qh + g);
        *(uint4*)(smem + FQL + off) = *(const uint4*)(g_ql + g);
    }
    CP_WAIT0();
    __syncthreads();

    // Q fragments held in registers for all 32 tiles
    uint32_t qh[4][4], ql[4][4];
#pragma unroll
    for (int kb = 0; kb < 4; kb++) {
        uint32_t ro = (uint32_t)((wr0 + lrA) * GP + kb * 16 + lcA) * 2;
        ldm4(qh[kb], sb + FQH + ro);
        ldm4(ql[kb], sb + FQL + ro);
    }

    float o[8][4];
#pragma unroll
    for (int a = 0; a < 8; a++)
#pragma unroll
        for (int d = 0; d < 4; d++) o[a][d] = 0.f;
    float l0 = 0.f, l1 = 0.f;

    // per-thread constant offset into the staged bias window
    const int off0 = 127 + (lane & 3) * 2 - wr0 - (lane >> 2);

    int cur = 0;
    for (int kt = 0; kt < 32; kt++) {
        if (kt < 31) loadkv(kt + 1, cur ^ 1);
        const uint32_t kvb = sb + FKV0 + cur * FSTG;
        const float* stab = (const float*)(smem + FTAB + cur * 768);

        // ---- S = Q K^T (3-term split) ----
        float sc[8][4];
#pragma unroll
        for (int a = 0; a < 8; a++)
#pragma unroll
            for (int d = 0; d < 4; d++) sc[a][d] = 0.f;
#pragma unroll
        for (int kb = 0; kb < 4; kb++) {
#pragma unroll
            for (int nb2 = 0; nb2 < 4; nb2++) {
                uint32_t bh[4], bl[4];
                uint32_t ro = (uint32_t)((nb2 * 16 + lrB) * GP + kb * 16 + lcB) * 2;
                ldm4(bh, kvb + FKH + ro);
                ldm4(bl, kvb + FKL + ro);
                mma16816(sc[nb2 * 2 + 0], qh[kb], bh);
                mma16816(sc[nb2 * 2 + 0], qh[kb], bl);
                mma16816(sc[nb2 * 2 + 0], ql[kb], bh);
                mma16816(sc[nb2 * 2 + 1], qh[kb], bh + 2);
                mma16816(sc[nb2 * 2 + 1], qh[kb], bl + 2);
                mma16816(sc[nb2 * 2 + 1], ql[kb], bh + 2);
            }
        }

        // ---- softmax (fixed shift), bias from smem window ----
        uint32_t pa[4][4], pl[4][4];
#pragma unroll
        for (int nb = 0; nb < 8; nb++) {
            int j = off0 + nb * 8;
            float p00 = __expf(sc[nb][0] + stab[j]);
            float p01 = __expf(sc[nb][1] + stab[j + 1]);
            float p10 = __expf(sc[nb][2] + stab[j - 8]);
            float p11 = __expf(sc[nb][3] + stab[j - 7]);
            l0 += p00 + p01;
            l1 += p10 + p11;
            uint32_t u0 = pack_bf16x2(p00, p01);
            uint32_t u1 = pack_bf16x2(p10, p11);
            int kb = nb >> 1, sl = (nb & 1) * 2;
            pa[kb][sl + 0] = u0;
            pa[kb][sl + 1] = u1;
            pl[kb][sl + 0] = pack_bf16x2(p00 - lo_f32(u0), p01 - hi_f32(u0));
            pl[kb][sl + 1] = pack_bf16x2(p10 - lo_f32(u1), p11 - hi_f32(u1));
        }

        // ---- O += P V (3-term split) ----
#pragma unroll
        for (int kb = 0; kb < 4; kb++) {
#pragma unroll
            for (int nb2 = 0; nb2 < 4; nb2++) {
                uint32_t vh[4], vl[4];
                uint32_t ro = (uint32_t)((kb * 16 + lrA) * GP + nb2 * 16 + lcA) * 2;
                ldm4t(vh, kvb + FVH + ro);
                ldm4t(vl, kvb + FVL + ro);
                mma16816(o[nb2 * 2 + 0], pa[kb], vh);
                mma16816(o[nb2 * 2 + 0], pa[kb], vl);
                mma16816(o[nb2 * 2 + 0], pl[kb], vh);
                mma16816(o[nb2 * 2 + 1], pa[kb], vh + 2);
                mma16816(o[nb2 * 2 + 1], pa[kb], vl + 2);
                mma16816(o[nb2 * 2 + 1], pl[kb], vh + 2);
            }
        }
        if (kt < 31) CP_WAIT0();
        __syncthreads();
        cur ^= 1;
    }

    // reduce row sums over the 4-lane quads, normalize, store split bf16
    l0 += __shfl_xor_sync(0xffffffffu, l0, 1);
    l0 += __shfl_xor_sync(0xffffffffu, l0, 2);
    l1 += __shfl_xor_sync(0xffffffffu, l1, 1);
    l1 += __shfl_xor_sync(0xffffffffu, l1, 2);
    float inv0 = 1.0f / l0, inv1 = 1.0f / l1;
    const int rg = rowbase + q0 + wr0 + (lane >> 2);
#pragma unroll
    for (int nb = 0; nb < 8; nb++) {
        int cg = h * HDIM + nb * 8 + (lane & 3) * 2;
        split_store2(g_aoh, g_aol, (size_t)rg * EMB + cg,
                     o[nb][0] * inv0, o[nb][1] * inv0);
        split_store2(g_aoh, g_aol, (size_t)(rg + 8) * EMB + cg,
                     o[nb][2] * inv1, o[nb][3] * inv1);
    }
}

// ---------------- launch ----------------------------------------------------
extern "C" void kernel_launch(void* const* d_in, const int* in_sizes, int n_in,
                              void* d_out, int out_size) {
    (void)in_sizes; (void)n_in; (void)out_size;
    const float* x   = (const float*)d_in[0];
    const float* Wq  = (const float*)d_in[1];
    const float* Wk  = (const float*)d_in[2];
    const float* Wv  = (const float*)d_in[3];
    const float* Wo  = (const float*)d_in[4];
    const float* rel = (const float*)d_in[5];

    float* out  = (float*)d_out;
    float* bias = out + OUT_ELEMS;

    prep_kernel<<<8448, 256>>>(x, Wq, Wk, Wv, Wo, rel);

    cudaFuncSetAttribute(qkv_mma_kernel, cudaFuncAttributeMaxDynamicSharedMemorySize, GEMM_SMEM);
    cudaFuncSetAttribute(out_mma_kernel, cudaFuncAttributeMaxDynamicSharedMemorySize, GEMM_SMEM);
    cudaFuncSetAttribute(flash_kernel, cudaFuncAttributeMaxDynamicSharedMemorySize, SMEM_FLASH);

    qkv_mma_kernel<<<dim3(8, 32, 3), 256, GEMM_SMEM>>>(bias);
    flash_kernel<<<dim3(SLEN / 128, HEADS, BATCH), 256, SMEM_FLASH>>>();
    out_mma_kernel<<<dim3(8, 32), 256, GEMM_SMEM>>>(out);
}

// round 17
// speedup vs baseline: 1.2293x; 1.0060x over previous
#include <cuda_runtime.h>
#include <cuda_bf16.h>
#include <math.h>
#include <stdint.h>

#define BATCH 2
#define SLEN  2048
#define HEADS 16
#define HDIM  64
#define EMB   1024
#define ROWS_TOT (BATCH*SLEN)        /* 4096 */
#define OUT_ELEMS (ROWS_TOT*EMB)
#define TABW  4095
#define MSHIFT 20.0f
#define LOG2E 1.4426950408889634f
#define GP 72                         /* flash smem row pitch in bf16 elems */

// ---------------- scratch (device globals) ---------------------------------
__device__ __nv_bfloat16 g_xh[ROWS_TOT*EMB],  g_xl[ROWS_TOT*EMB];
__device__ __nv_bfloat16 g_whi[4*EMB*EMB],    g_wlo[4*EMB*EMB];   // [n][k]
__device__ __nv_bfloat16 g_qh[ROWS_TOT*EMB],  g_ql[ROWS_TOT*EMB];
__device__ __nv_bfloat16 g_kh[ROWS_TOT*EMB],  g_kl[ROWS_TOT*EMB];
__device__ __nv_bfloat16 g_vh[ROWS_TOT*EMB],  g_vl[ROWS_TOT*EMB];
__device__ __nv_bfloat16 g_aoh[ROWS_TOT*EMB], g_aol[ROWS_TOT*EMB];
__device__ float g_tab[HEADS*TABW];
__device__ float g_tab2[HEADS*TABW];   // (bias - MSHIFT) * log2(e)

// ---------------- helpers ---------------------------------------------------
static __device__ __forceinline__ uint32_t smem_u32(const void* p) {
    return (uint32_t)__cvta_generic_to_shared(p);
}
static __device__ __forceinline__ void cpa16(uint32_t s, const void* g) {
    asm volatile("cp.async.cg.shared.global [%0], [%1], 16;" :: "r"(s), "l"(g));
}
static __device__ __forceinline__ void cpa4(uint32_t s, const void* g) {
    asm volatile("cp.async.ca.shared.global [%0], [%1], 4;" :: "r"(s), "l"(g));
}
#define CP_COMMIT() asm volatile("cp.async.commit_group;" ::: "memory")
#define CP_WAIT0()  asm volatile("cp.async.wait_group 0;" ::: "memory")
#define CP_WAIT1()  asm volatile("cp.async.wait_group 1;" ::: "memory")
static __device__ __forceinline__ void ldm4(uint32_t* r, uint32_t a) {
    asm volatile("ldmatrix.sync.aligned.m8n8.x4.shared.b16 {%0,%1,%2,%3}, [%4];"
        : "=r"(r[0]), "=r"(r[1]), "=r"(r[2]), "=r"(r[3]) : "r"(a));
}
static __device__ __forceinline__ void ldm4t(uint32_t* r, uint32_t a) {
    asm volatile("ldmatrix.sync.aligned.m8n8.x4.trans.shared.b16 {%0,%1,%2,%3}, [%4];"
        : "=r"(r[0]), "=r"(r[1]), "=r"(r[2]), "=r"(r[3]) : "r"(a));
}
static __device__ __forceinline__ void mma16816(float* c, const uint32_t* a, const uint32_t* b) {
    asm volatile(
        "mma.sync.aligned.m16n8k16.row.col.f32.bf16.bf16.f32 "
        "{%0,%1,%2,%3}, {%4,%5,%6,%7}, {%8,%9}, {%0,%1,%2,%3};"
        : "+f"(c[0]), "+f"(c[1]), "+f"(c[2]), "+f"(c[3])
        : "r"(a[0]), "r"(a[1]), "r"(a[2]), "r"(a[3]), "r"(b[0]), "r"(b[1]));
}
static __device__ __forceinline__ uint32_t pack_bf16x2(float lo, float hi) {
    __nv_bfloat162 t = __floats2bfloat162_rn(lo, hi);
    return *reinterpret_cast<uint32_t*>(&t);
}
static __device__ __forceinline__ float lo_f32(uint32_t u) { return __uint_as_float(u << 16); }
static __device__ __forceinline__ float hi_f32(uint32_t u) { return __uint_as_float(u & 0xffff0000u); }
static __device__ __forceinline__ void split_store2(__nv_bfloat16* H, __nv_bfloat16* L,
                                                    size_t idx, float v0, float v1) {
    __nv_bfloat162 hh = __floats2bfloat162_rn(v0, v1);
    __nv_bfloat162 ll = __floats2bfloat162_rn(v0 - __bfloat162float(hh.x),
                                              v1 - __bfloat162float(hh.y));
    *reinterpret_cast<__nv_bfloat162*>(H + idx) = hh;
    *reinterpret_cast<__nv_bfloat162*>(L + idx) = ll;
}

// ---------------- T5 bucket -------------------------------------------------
__device__ __forceinline__ int rel_bucket(int d) {
    int base = (d > 0) ? 16 : 0;
    int rp = abs(d);
    if (rp < 8) return base + rp;
    double v = log((double)rp / 8.0) / log(16.0) * 8.0;
    int b = (int)(v + 1e-6);
    if (b > 7) b = 7;
    return base + 8 + b;
}

// ---------------- fused prep: bias table + x split + W split ----------------
// grid.x partition: [0,256) build_tab, [256,4352) xsplit, [4352,8448) wsplit
__global__ __launch_bounds__(256) void prep_kernel(const float* __restrict__ x,
                                                   const float* __restrict__ W0,
                                                   const float* __restrict__ W1,
                                                   const float* __restrict__ W2,
                                                   const float* __restrict__ W3,
                                                   const float* __restrict__ rel) {
    const int b = blockIdx.x, tid = threadIdx.x;
    if (b < 256) {
        int idx = b * 256 + tid;
        if (idx < HEADS * TABW) {
            int h = idx / TABW, dd = idx % TABW;
            float v = rel[rel_bucket(dd - 2047) * HEADS + h];
            g_tab[h * TABW + dd]  = v;
            g_tab2[h * TABW + dd] = (v - MSHIFT) * LOG2E;
        }
    } else if (b < 256 + 4096) {
        int idx = (b - 256) * 256 + tid;    // float4 id
        float4 v = reinterpret_cast<const float4*>(x)[idx];
        __nv_bfloat162 h0 = __floats2bfloat162_rn(v.x, v.y);
        __nv_bfloat162 h1 = __floats2bfloat162_rn(v.z, v.w);
        __nv_bfloat162 l0 = __floats2bfloat162_rn(v.x - __bfloat162float(h0.x),
                                                  v.y - __bfloat162float(h0.y));
        __nv_bfloat162 l1 = __floats2bfloat162_rn(v.z - __bfloat162float(h1.x),
                                                  v.w - __bfloat162float(h1.y));
        reinterpret_cast<__nv_bfloat162*>(g_xh)[idx * 2]     = h0;
        reinterpret_cast<__nv_bfloat162*>(g_xh)[idx * 2 + 1] = h1;
        reinterpret_cast<__nv_bfloat162*>(g_xl)[idx * 2]     = l0;
        reinterpret_cast<__nv_bfloat162*>(g_xl)[idx * 2 + 1] = l1;
    } else {
        __shared__ float t[32][33];
        int idx = b - 4352;
        int z = idx >> 10, ny = (idx >> 5) & 31, nx = idx & 31;
        const float* W = (z == 0) ? W0 : (z == 1) ? W1 : (z == 2) ? W2 : W3;
        int n0 = nx * 32, k0 = ny * 32;
        int tx = tid & 31, ty = tid >> 5;
#pragma unroll
        for (int i = ty; i < 32; i += 8)
            t[i][tx] = W[(size_t)(k0 + i) * EMB + n0 + tx];
        __syncthreads();
        __nv_bfloat16* hi = g_whi + (size_t)z * EMB * EMB;
        __nv_bfloat16* lo = g_wlo + (size_t)z * EMB * EMB;
#pragma unroll
        for (int i = ty; i < 32; i += 8) {
            float v = t[tx][i];
            __nv_bfloat16 h = __float2bfloat16(v);
            size_t o = (size_t)(n0 + i) * EMB + k0 + tx;
            hi[o] = h;
            lo[o] = __float2bfloat16(v - __bfloat162float(h));
        }
    }
}

// ---------------- tensor-core GEMM: XOR-swizzled, 3-stage cp.async ----------
#define KC 32
#define GT 8192                        /* one 128x32 bf16 tile */
#define GAH 0
#define GAL GT
#define GBH (2*GT)
#define GBL (3*GT)
#define GSTAGEB (4*GT)                 /* 32768 */
#define GEMM_SMEM (3*GSTAGEB)          /* 98304 */

__device__ __forceinline__ void gemm_body(
    const __nv_bfloat16* __restrict__ Ah, const __nv_bfloat16* __restrict__ Al,
    const __nv_bfloat16* __restrict__ Bh, const __nv_bfloat16* __restrict__ Bl,
    __nv_bfloat16* __restrict__ Oh, __nv_bfloat16* __restrict__ Ol,
    float* __restrict__ Of, float* __restrict__ bias)
{
    extern __shared__ __align__(16) char smem[];
    const uint32_t sb = smem_u32(smem);
    const int tid = threadIdx.x, lane = tid & 31, wid = tid >> 5;
    const int wm = wid >> 2, wn = wid & 3;
    const int row0 = blockIdx.y * 128, col0 = blockIdx.x * 128;

    const int lrA = (lane & 7) + ((lane >> 3) & 1) * 8;   // A-frag row in 16
    const int lrB = (lane & 7) + ((lane >> 4) << 3);      // B-frag row in 16
    const int swA = (lrA >> 1) & 3, ccA = lane >> 4;        // swizzle consts
    const int swB = (lrB >> 1) & 3, ccB = (lane >> 3) & 1;

    // bias stream base (qkv only)
    const uint32_t bbase = ((uint32_t)blockIdx.z * 256u + (uint32_t)blockIdx.y * 8u
                            + (uint32_t)blockIdx.x) * 256u + (uint32_t)tid;

    float c[4][4][4];
#pragma unroll
    for (int a = 0; a < 4; a++)
#pragma unroll
        for (int b = 0; b < 4; b++)
#pragma unroll
            for (int d = 0; d < 4; d++) c[a][b][d] = 0.f;

    auto loadch = [&](int k0, int s) {
        uint32_t b = sb + s * GSTAGEB;
#pragma unroll
        for (int t = 0; t < 2; t++) {
            int fi = tid + t * 256;
            int r = fi >> 2, ck = fi & 3;
            uint32_t so = (uint32_t)(r * 64 + ((ck ^ ((r >> 1) & 3)) << 4));
            size_t ga = (size_t)(row0 + r) * EMB + k0 + ck * 8;
            size_t gb = (size_t)(col0 + r) * EMB + k0 + ck * 8;
            cpa16(b + GAH + so, Ah + ga);
            cpa16(b + GAL + so, Al + ga);
            cpa16(b + GBH + so, Bh + gb);
            cpa16(b + GBL + so, Bl + gb);
        }
        CP_COMMIT();
    };

    loadch(0, 0);
    loadch(KC, 1);
    CP_WAIT1();              // chunk 0 resident
    __syncthreads();

    for (int ch = 0; ch < 32; ch++) {
        if (ch + 2 < 32) loadch((ch + 2) * KC, (ch + 2) % 3);

        // interleaved position_bias stores (fire-and-forget, overlaps MMAs)
        if (bias) {
#pragma unroll
            for (int j = 0; j < 3; j++) {
                uint32_t i = bbase + (uint32_t)(ch * 3 + j) * 196608u;
                if (i < 16777216u) {
                    uint32_t k4 = i & 511, q = (i >> 9) & 2047, h = i >> 20;
                    int d = (int)(k4 << 2) - (int)q + 2047;
                    const float* t = g_tab + h * TABW + d;
                    float4 v = make_float4(__ldg(t), __ldg(t + 1),
                                           __ldg(t + 2), __ldg(t + 3));
                    __stcs(reinterpret_cast<float4*>(bias) + i, v);
                }
            }
        }

        const uint32_t base = sb + (ch % 3) * GSTAGEB;
#pragma unroll
        for (int kk = 0; kk < 2; kk++) {
            uint32_t ah[4][4], al_[4][4];
#pragma unroll
            for (int mi = 0; mi < 4; mi++) {
                uint32_t ro = (uint32_t)((wm * 64 + mi * 16 + lrA) * 64
                                         + (((kk * 2 + ccA) ^ swA) << 4));
                ldm4(ah[mi],  base + GAH + ro);
                ldm4(al_[mi], base + GAL + ro);
            }
#pragma unroll
            for (int nj2 = 0; nj2 < 2; nj2++) {
                uint32_t bh[4], bl[4];
                uint32_t ro = (uint32_t)((wn * 32 + nj2 * 16 + lrB) * 64
                                         + (((kk * 2 + ccB) ^ swB) << 4));
                ldm4(bh, base + GBH + ro);
                ldm4(bl, base + GBL + ro);
#pragma unroll
                for (int mi = 0; mi < 4; mi++) {
                    mma16816(c[mi][nj2 * 2 + 0], ah[mi],  bh);
                    mma16816(c[mi][nj2 * 2 + 0], ah[mi],  bl);
                    mma16816(c[mi][nj2 * 2 + 0], al_[mi], bh);
                    mma16816(c[mi][nj2 * 2 + 1], ah[mi],  bh + 2);
                    mma16816(c[mi][nj2 * 2 + 1], ah[mi],  bl + 2);
                    mma16816(c[mi][nj2 * 2 + 1], al_[mi], bh + 2);
                }
            }
        }
        if (ch + 1 < 32) {
            if (ch + 2 < 32) { CP_WAIT1(); } else { CP_WAIT0(); }
            __syncthreads();
        }
    }

#pragma unroll
    for (int mi = 0; mi < 4; mi++)
#pragma unroll
        for (int nj = 0; nj < 4; nj++) {
            int rg = row0 + wm * 64 + mi * 16 + (lane >> 2);
            int cg = col0 + wn * 32 + nj * 8 + (lane & 3) * 2;
            size_t i0 = (size_t)rg * EMB + cg, i1 = (size_t)(rg + 8) * EMB + cg;
            if (Of) {
                *(float2*)(Of + i0) = make_float2(c[mi][nj][0], c[mi][nj][1]);
                *(float2*)(Of + i1) = make_float2(c[mi][nj][2], c[mi][nj][3]);
            } else {
                split_store2(Oh, Ol, i0, c[mi][nj][0], c[mi][nj][1]);
                split_store2(Oh, Ol, i1, c[mi][nj][2], c[mi][nj][3]);
            }
        }
}

__global__ __launch_bounds__(256, 2) void qkv_mma_kernel(float* __restrict__ bias) {
    int z = blockIdx.z;
    __nv_bfloat16* Oh = (z == 0) ? g_qh : (z == 1) ? g_kh : g_vh;
    __nv_bfloat16* Ol = (z == 0) ? g_ql : (z == 1) ? g_kl : g_vl;
    gemm_body(g_xh, g_xl, g_whi + (size_t)z * EMB * EMB, g_wlo + (size_t)z * EMB * EMB,
              Oh, Ol, nullptr, bias);
}
__global__ __launch_bounds__(256, 2) void out_mma_kernel(float* __restrict__ out) {
    gemm_body(g_aoh, g_aol, g_whi + (size_t)3 * EMB * EMB, g_wlo + (size_t)3 * EMB * EMB,
              nullptr, nullptr, out, nullptr);
}

// ---------------- flash attention: 3-stage KV ring (Q smem reused) ----------
// Stage s at s*FSTG; Q staged in stage 0 during prologue, then recycled.
#define FSTG 36864
#define FKH  0
#define FKL  9216
#define FVH  18432
#define FVL  27648
#define FTAB (3*FSTG)                 /* bias windows: 3 stages x 192 floats */
#define SMEM_FLASH (FTAB + 3*192*4)   /* 112896 */

__global__ __launch_bounds__(256, 2) void flash_kernel() {
    extern __shared__ __align__(16) char smem[];
    const uint32_t sb = smem_u32(smem);
    const int tid = threadIdx.x, lane = tid & 31, wid = tid >> 5;
    const int wr0 = wid * 16;
    const int q0 = blockIdx.x * 128, h = blockIdx.y, rowbase = blockIdx.z * SLEN;
    const float* tabh = g_tab2 + h * TABW;

    const int lrA = (lane & 7) + ((lane >> 3) & 1) * 8;
    const int lcA = (lane >> 4) * 8;
    const int lrB = (lane & 7) + ((lane >> 4) << 3);
    const int lcB = ((lane >> 3) & 1) * 8;

    auto loadkv = [&](int kt, int s) {
        const int k0 = kt * 64;
        uint32_t b = sb + s * FSTG;
#pragma unroll
        for (int t = 0; t < 2; t++) {
            int fi = tid + t * 256;
            int r = fi >> 3, c8 = (fi & 7) * 8;
            uint32_t so = (uint32_t)(r * GP + c8) * 2;
            size_t g = (size_t)(rowbase + k0 + r) * EMB + h * HDIM + c8;
            cpa16(b + FKH + so, g_kh + g);
            cpa16(b + FKL + so, g_kl + g);
            cpa16(b + FVH + so, g_vh + g);
            cpa16(b + FVL + so, g_vl + g);
        }
        if (tid < 192) {     // stage this tile's 192-float bias window
            int idx = (k0 - q0 + 1920) + tid;
            if (idx > TABW - 1) idx = TABW - 1;
            cpa4(sb + FTAB + s * 768 + tid * 4, tabh + idx);
        }
        CP_COMMIT();
    };

    // ---- prologue: stage Q in stage-0 area, extract fragments, then recycle
#pragma unroll
    for (int t = 0; t < 4; t++) {
        int fi = tid + t * 256, r = fi >> 3, c8 = (fi & 7) * 8;
        size_t g = (size_t)(rowbase + q0 + r) * EMB + h * HDIM + c8;
        uint32_t off = (uint32_t)(r * GP + c8) * 2;
        *(uint4*)(smem + off)         = *(const uint4*)(g_qh + g);
        *(uint4*)(smem + 18432 + off) = *(const uint4*)(g_ql + g);
    }
    __syncthreads();

    uint32_t qh[4][4], ql[4][4];
#pragma unroll
    for (int kb = 0; kb < 4; kb++) {
        uint32_t ro = (uint32_t)((wr0 + lrA) * GP + kb * 16 + lcA) * 2;
        ldm4(qh[kb], sb + ro);
        ldm4(ql[kb], sb + 18432 + ro);
    }
    __syncthreads();         // all warps done reading Q before stage 0 reuse

    loadkv(0, 0);
    loadkv(1, 1);
    CP_WAIT1();              // tile 0 resident
    __syncthreads();

    float o[8][4];
#pragma unroll
    for (int a = 0; a < 8; a++)
#pragma unroll
        for (int d = 0; d < 4; d++) o[a][d] = 0.f;
    float l0 = 0.f, l1 = 0.f;

    // per-thread constant offset into the staged bias window
    const int off0 = 127 + (lane & 3) * 2 - wr0 - (lane >> 2);

    for (int kt = 0; kt < 32; kt++) {
        if (kt + 2 < 32) loadkv(kt + 2, (kt + 2) % 3);
        const uint32_t kvb = sb + (kt % 3) * FSTG;
        const float* stab = (const float*)(smem + FTAB + (kt % 3) * 768);

        // ---- S = Q K^T (3-term split) ----
        float sc[8][4];
#pragma unroll
        for (int a = 0; a < 8; a++)
#pragma unroll
            for (int d = 0; d < 4; d++) sc[a][d] = 0.f;
#pragma unroll
        for (int kb = 0; kb < 4; kb++) {
#pragma unroll
            for (int nb2 = 0; nb2 < 4; nb2++) {
                uint32_t bh[4], bl[4];
                uint32_t ro = (uint32_t)((nb2 * 16 + lrB) * GP + kb * 16 + lcB) * 2;
                ldm4(bh, kvb + FKH + ro);
                ldm4(bl, kvb + FKL + ro);
                mma16816(sc[nb2 * 2 + 0], qh[kb], bh);
                mma16816(sc[nb2 * 2 + 0], qh[kb], bl);
                mma16816(sc[nb2 * 2 + 0], ql[kb], bh);
                mma16816(sc[nb2 * 2 + 1], qh[kb], bh + 2);
                mma16816(sc[nb2 * 2 + 1], qh[kb], bl + 2);
                mma16816(sc[nb2 * 2 + 1], ql[kb], bh + 2);
            }
        }

        // ---- softmax: p = 2^(s*log2e + tab'), tab' pre-scaled ----
        uint32_t pa[4][4], pl[4][4];
#pragma unroll
        for (int nb = 0; nb < 8; nb++) {
            int j = off0 + nb * 8;
            float p00 = exp2f(fmaf(sc[nb][0], LOG2E, stab[j]));
            float p01 = exp2f(fmaf(sc[nb][1], LOG2E, stab[j + 1]));
            float p10 = exp2f(fmaf(sc[nb][2], LOG2E, stab[j - 8]));
            float p11 = exp2f(fmaf(sc[nb][3], LOG2E, stab[j - 7]));
            l0 += p00 + p01;
            l1 += p10 + p11;
            uint32_t u0 = pack_bf16x2(p00, p01);
            uint32_t u1 = pack_bf16x2(p10, p11);
            int kb = nb >> 1, sl = (nb & 1) * 2;
            pa[kb][sl + 0] = u0;
            pa[kb][sl + 1] = u1;
            pl[kb][sl + 0] = pack_bf16x2(p00 - lo_f32(u0), p01 - hi_f32(u0));
            pl[kb][sl + 1] = pack_bf16x2(p10 - lo_f32(u1), p11 - hi_f32(u1));
        }

        // ---- O += P V (3-term split) ----
#pragma unroll
        for (int kb = 0; kb < 4; kb++) {
#pragma unroll
            for (int nb2 = 0; nb2 < 4; nb2++) {
                uint32_t vh[4], vl[4];
                uint32_t ro = (uint32_t)((kb * 16 + lrA) * GP + nb2 * 16 + lcA) * 2;
                ldm4t(vh, kvb + FVH + ro);
                ldm4t(vl, kvb + FVL + ro);
                mma16816(o[nb2 * 2 + 0], pa[kb], vh);
                mma16816(o[nb2 * 2 + 0], pa[kb], vl);
                mma16816(o[nb2 * 2 + 0], pl[kb], vh);
                mma16816(o[nb2 * 2 + 1], pa[kb], vh + 2);
                mma16816(o[nb2 * 2 + 1], pa[kb], vl + 2);
                mma16816(o[nb2 * 2 + 1], pl[kb], vh + 2);
            }
        }
        if (kt + 1 < 32) {
            if (kt + 2 < 32) { CP_WAIT1(); } else { CP_WAIT0(); }
            __syncthreads();
        }
    }

    // reduce row sums over the 4-lane quads, normalize, store split bf16
    l0 += __shfl_xor_sync(0xffffffffu, l0, 1);
    l0 += __shfl_xor_sync(0xffffffffu, l0, 2);
    l1 += __shfl_xor_sync(0xffffffffu, l1, 1);
    l1 += __shfl_xor_sync(0xffffffffu, l1, 2);
    float inv0 = 1.0f / l0, inv1 = 1.0f / l1;
    const int rg = rowbase + q0 + wr0 + (lane >> 2);
#pragma unroll
    for (int nb = 0; nb < 8; nb++) {
        int cg = h * HDIM + nb * 8 + (lane & 3) * 2;
        split_store2(g_aoh, g_aol, (size_t)rg * EMB + cg,
                     o[nb][0] * inv0, o[nb][1] * inv0);
        split_store2(g_aoh, g_aol, (size_t)(rg + 8) * EMB + cg,
                     o[nb][2] * inv1, o[nb][3] * inv1);
    }
}

// ---------------- launch ----------------------------------------------------
extern "C" void kernel_launch(void* const* d_in, const int* in_sizes, int n_in,
                              void* d_out, int out_size) {
    (void)in_sizes; (void)n_in; (void)out_size;
    const float* x   = (const float*)d_in[0];
    const float* Wq  = (const float*)d_in[1];
    const float* Wk  = (const float*)d_in[2];
    const float* Wv  = (const float*)d_in[3];
    const float* Wo  = (const float*)d_in[4];
    const float* rel = (const float*)d_in[5];

    float* out  = (float*)d_out;
    float* bias = out + OUT_ELEMS;

    prep_kernel<<<8448, 256>>>(x, Wq, Wk, Wv, Wo, rel);

    cudaFuncSetAttribute(qkv_mma_kernel, cudaFuncAttributeMaxDynamicSharedMemorySize, GEMM_SMEM);
    cudaFuncSetAttribute(out_mma_kernel, cudaFuncAttributeMaxDynamicSharedMemorySize, GEMM_SMEM);
    cudaFuncSetAttribute(flash_kernel, cudaFuncAttributeMaxDynamicSharedMemorySize, SMEM_FLASH);

    qkv_mma_kernel<<<dim3(8, 32, 3), 256, GEMM_SMEM>>>(bias);
    flash_kernel<<<dim3(SLEN / 128, HEADS, BATCH), 256, SMEM_FLASH>>>();
    out_mma_kernel<<<dim3(8, 32), 256, GEMM_SMEM>>>(out);
}